// round 1
// baseline (speedup 1.0000x reference)
#include <cuda_runtime.h>

// Problem constants
#define NB   4
#define NS   2048
#define NDM  1024
#define NH   16
#define NDK  64
#define NM   (NB * NS)      // 8192 rows

// ---------------------------------------------------------------------------
// Device scratch (no allocations allowed in kernel_launch)
// ---------------------------------------------------------------------------
__device__ float g_Qh[NB * NH * NS * NDK];   // [B,H,S,64]
__device__ float g_Kh[NB * NH * NS * NDK];
__device__ float g_Vh[NB * NH * NS * NDK];
__device__ float g_ctx[NM * NDM];            // [B*S, H*Dv]

// ---------------------------------------------------------------------------
// Tiled fp32 GEMM: C[M=8192, N=1024] = A[M,1024] @ W[1024,1024]
// BM=BN=64, BK=16, 256 threads, 4x4 microtile per thread.
// HEADS=true  -> write C into [B,H,S,64] layout (one head per block column)
// HEADS=false -> plain row-major [M, 1024]
// ---------------------------------------------------------------------------
template <bool HEADS>
__global__ __launch_bounds__(256) void gemm64(const float* __restrict__ A,
                                              const float* __restrict__ W,
                                              float* __restrict__ C) {
    __shared__ float As[16][68];   // transposed A tile [k][m], padded (2-way max)
    __shared__ float Bs[16][64];   // B tile [k][n]

    const int tid = threadIdx.x;
    const int tx  = tid & 15;
    const int ty  = tid >> 4;
    const int m0  = blockIdx.y * 64;
    const int n0  = blockIdx.x * 64;

    // load mapping
    const int arow = tid >> 2;          // 0..63
    const int acol = (tid & 3) << 2;    // 0,4,8,12
    const int brow = tid >> 4;          // 0..15
    const int bcol = (tid & 15) << 2;   // 0..60

    const float* Aptr = A + (m0 + arow) * NDM + acol;
    const float* Wptr = W + brow * NDM + n0 + bcol;

    float acc[4][4];
#pragma unroll
    for (int i = 0; i < 4; i++)
#pragma unroll
        for (int j = 0; j < 4; j++) acc[i][j] = 0.f;

    for (int k0 = 0; k0 < NDM; k0 += 16) {
        float4 av = *(const float4*)(Aptr + k0);
        float4 bv = *(const float4*)(Wptr + (size_t)k0 * NDM);
        __syncthreads();
        As[acol + 0][arow] = av.x;
        As[acol + 1][arow] = av.y;
        As[acol + 2][arow] = av.z;
        As[acol + 3][arow] = av.w;
        *(float4*)&Bs[brow][bcol] = bv;
        __syncthreads();
#pragma unroll
        for (int kk = 0; kk < 16; kk++) {
            float4 a = *(const float4*)&As[kk][ty << 2];
            float4 b = *(const float4*)&Bs[kk][tx << 2];
            float ar[4] = {a.x, a.y, a.z, a.w};
            float br[4] = {b.x, b.y, b.z, b.w};
#pragma unroll
            for (int i = 0; i < 4; i++)
#pragma unroll
                for (int j = 0; j < 4; j++)
                    acc[i][j] = fmaf(ar[i], br[j], acc[i][j]);
        }
    }

#pragma unroll
    for (int i = 0; i < 4; i++) {
        const int m = m0 + (ty << 2) + i;
        float4 v = make_float4(acc[i][0], acc[i][1], acc[i][2], acc[i][3]);
        if (HEADS) {
            const int b = m >> 11;        // m / 2048
            const int s = m & 2047;
            const int h = blockIdx.x;     // BN == 64 == head dim
            const int idx = (((b * NH + h) * NS + s) << 6) + (tx << 2);
            *(float4*)&C[idx] = v;
        } else {
            *(float4*)&C[(size_t)m * NDM + n0 + (tx << 2)] = v;
        }
    }
}

// ---------------------------------------------------------------------------
// Flash attention, causal. One CTA per (q-tile of 64, b*h).
// Tiles: Qst [d][q] (transposed), KP [d][k] transposed K then reused as P[k][q],
// Vs [k][d] natural. Online softmax in registers; 4x4 microtile per thread.
// ---------------------------------------------------------------------------
#define ATTN_PAD 68
#define ATTN_SMEM_FLOATS (2 * 64 * ATTN_PAD + 64 * 64)

__global__ __launch_bounds__(256) void attn_kernel(const float* __restrict__ Qh,
                                                   const float* __restrict__ Kh,
                                                   const float* __restrict__ Vh,
                                                   float* __restrict__ ctx) {
    extern __shared__ float smem[];
    float(*Qst)[ATTN_PAD] = (float(*)[ATTN_PAD])smem;                      // [d][q]
    float(*KP)[ATTN_PAD]  = (float(*)[ATTN_PAD])(smem + 64 * ATTN_PAD);    // [d][k] / P[k][q]
    float(*Vs)[64]        = (float(*)[64])(smem + 2 * 64 * ATTN_PAD);      // [k][d]

    const int tid = threadIdx.x;
    const int tx  = tid & 15;
    const int ty  = tid >> 4;
    const int qt  = blockIdx.x;
    const int bh  = blockIdx.y;

    const float* Qb = Qh + (size_t)bh * NS * 64;
    const float* Kb = Kh + (size_t)bh * NS * 64;
    const float* Vb = Vh + (size_t)bh * NS * 64;

    const int lr = tid >> 4;          // 0..15
    const int lc = (tid & 15) << 2;   // 0..60

    // Load Q tile transposed (once)
#pragma unroll
    for (int it = 0; it < 4; it++) {
        const int r = lr + it * 16;
        float4 q = *(const float4*)(Qb + (size_t)(qt * 64 + r) * 64 + lc);
        Qst[lc + 0][r] = q.x;
        Qst[lc + 1][r] = q.y;
        Qst[lc + 2][r] = q.z;
        Qst[lc + 3][r] = q.w;
    }

    float o[4][4];
    float mrow[4], lsum[4];
#pragma unroll
    for (int i = 0; i < 4; i++) {
        mrow[i] = -1e30f;
        lsum[i] = 0.f;
#pragma unroll
        for (int j = 0; j < 4; j++) o[i][j] = 0.f;
    }

    for (int kt = 0; kt <= qt; kt++) {
        __syncthreads();   // previous PV done reading KP/Vs
        // Load K tile transposed + V tile natural
#pragma unroll
        for (int it = 0; it < 4; it++) {
            const int r = lr + it * 16;
            float4 kv = *(const float4*)(Kb + (size_t)(kt * 64 + r) * 64 + lc);
            KP[lc + 0][r] = kv.x;
            KP[lc + 1][r] = kv.y;
            KP[lc + 2][r] = kv.z;
            KP[lc + 3][r] = kv.w;
            float4 vv = *(const float4*)(Vb + (size_t)(kt * 64 + r) * 64 + lc);
            *(float4*)&Vs[r][lc] = vv;
        }
        __syncthreads();

        // S = Q K^T * scale
        float s[4][4];
#pragma unroll
        for (int i = 0; i < 4; i++)
#pragma unroll
            for (int j = 0; j < 4; j++) s[i][j] = 0.f;

#pragma unroll 16
        for (int kd = 0; kd < 64; kd++) {
            float4 a = *(const float4*)&Qst[kd][ty << 2];
            float4 b = *(const float4*)&KP[kd][tx << 2];
            float ar[4] = {a.x, a.y, a.z, a.w};
            float br[4] = {b.x, b.y, b.z, b.w};
#pragma unroll
            for (int i = 0; i < 4; i++)
#pragma unroll
                for (int j = 0; j < 4; j++)
                    s[i][j] = fmaf(ar[i], br[j], s[i][j]);
        }

#pragma unroll
        for (int i = 0; i < 4; i++)
#pragma unroll
            for (int j = 0; j < 4; j++) s[i][j] *= 0.125f;   // 1/sqrt(64)

        if (kt == qt) {
#pragma unroll
            for (int i = 0; i < 4; i++)
#pragma unroll
                for (int j = 0; j < 4; j++)
                    if ((tx << 2) + j > (ty << 2) + i) s[i][j] = -1e30f;
        }

        // Online softmax per q row. Row group = 16 consecutive lanes (same ty).
        float mnew[4], corr[4], rsum[4];
#pragma unroll
        for (int i = 0; i < 4; i++) {
            float mx = fmaxf(fmaxf(s[i][0], s[i][1]), fmaxf(s[i][2], s[i][3]));
#pragma unroll
            for (int off = 1; off < 16; off <<= 1)
                mx = fmaxf(mx, __shfl_xor_sync(0xffffffffu, mx, off));
            mnew[i] = fmaxf(mrow[i], mx);
            corr[i] = __expf(mrow[i] - mnew[i]);
            float rs = 0.f;
#pragma unroll
            for (int j = 0; j < 4; j++) {
                s[i][j] = __expf(s[i][j] - mnew[i]);
                rs += s[i][j];
            }
#pragma unroll
            for (int off = 1; off < 16; off <<= 1)
                rs += __shfl_xor_sync(0xffffffffu, rs, off);
            rsum[i] = rs;
        }

        __syncthreads();   // all threads done reading KP as K

        // Store P into KP as [k][q]
#pragma unroll
        for (int i = 0; i < 4; i++)
#pragma unroll
            for (int j = 0; j < 4; j++)
                KP[(tx << 2) + j][(ty << 2) + i] = s[i][j];

#pragma unroll
        for (int i = 0; i < 4; i++) {
            lsum[i] = lsum[i] * corr[i] + rsum[i];
            mrow[i] = mnew[i];
#pragma unroll
            for (int j = 0; j < 4; j++) o[i][j] *= corr[i];
        }
        __syncthreads();

        // O += P @ V
#pragma unroll 16
        for (int kk = 0; kk < 64; kk++) {
            float4 a = *(const float4*)&KP[kk][ty << 2];
            float4 b = *(const float4*)&Vs[kk][tx << 2];
            float ar[4] = {a.x, a.y, a.z, a.w};
            float br[4] = {b.x, b.y, b.z, b.w};
#pragma unroll
            for (int i = 0; i < 4; i++)
#pragma unroll
                for (int j = 0; j < 4; j++)
                    o[i][j] = fmaf(ar[i], br[j], o[i][j]);
        }
    }

    // Write ctx in [B*S, H*64] layout
    const int b = bh >> 4;
    const int h = bh & 15;
#pragma unroll
    for (int i = 0; i < 4; i++) {
        const float inv = 1.f / lsum[i];
        const int sg = qt * 64 + (ty << 2) + i;
        float4 v = make_float4(o[i][0] * inv, o[i][1] * inv, o[i][2] * inv, o[i][3] * inv);
        *(float4*)&ctx[(size_t)(b * NS + sg) * NDM + h * 64 + (tx << 2)] = v;
    }
}

// ---------------------------------------------------------------------------
// Fused residual + LayerNorm, in-place on out (out currently holds ctx @ W_O).
// One block per row; 256 threads * float4 = 1024 cols.
// ---------------------------------------------------------------------------
__global__ __launch_bounds__(256) void ln_kernel(const float* __restrict__ Qin,
                                                 const float* __restrict__ gamma,
                                                 const float* __restrict__ beta,
                                                 float* __restrict__ out) {
    __shared__ float rs[8], rq[8], fin[2];
    const int row = blockIdx.x;
    const int tid = threadIdx.x;
    const int c   = tid << 2;

    float4 o4 = *(const float4*)(out + (size_t)row * NDM + c);
    float4 q4 = *(const float4*)(Qin + (size_t)row * NDM + c);
    const float x0 = o4.x + q4.x, x1 = o4.y + q4.y, x2 = o4.z + q4.z, x3 = o4.w + q4.w;
    float s  = x0 + x1 + x2 + x3;
    float sq = x0 * x0 + x1 * x1 + x2 * x2 + x3 * x3;
#pragma unroll
    for (int off = 16; off; off >>= 1) {
        s  += __shfl_xor_sync(0xffffffffu, s, off);
        sq += __shfl_xor_sync(0xffffffffu, sq, off);
    }
    const int wid = tid >> 5, lane = tid & 31;
    if (lane == 0) { rs[wid] = s; rq[wid] = sq; }
    __syncthreads();
    if (tid == 0) {
        float a = 0.f, b2 = 0.f;
#pragma unroll
        for (int i = 0; i < 8; i++) { a += rs[i]; b2 += rq[i]; }
        fin[0] = a;
        fin[1] = b2;
    }
    __syncthreads();
    const float mu   = fin[0] * (1.0f / NDM);
    const float var  = fin[1] * (1.0f / NDM) - mu * mu;
    const float rstd = rsqrtf(var + 1e-5f);

    float4 g4 = *(const float4*)(gamma + c);
    float4 b4 = *(const float4*)(beta + c);
    float4 r;
    r.x = (x0 - mu) * rstd * g4.x + b4.x;
    r.y = (x1 - mu) * rstd * g4.y + b4.y;
    r.z = (x2 - mu) * rstd * g4.z + b4.z;
    r.w = (x3 - mu) * rstd * g4.w + b4.w;
    *(float4*)(out + (size_t)row * NDM + c) = r;
}

// ---------------------------------------------------------------------------
// Launch
// ---------------------------------------------------------------------------
extern "C" void kernel_launch(void* const* d_in, const int* in_sizes, int n_in,
                              void* d_out, int out_size) {
    const float* Q     = (const float*)d_in[0];
    const float* K     = (const float*)d_in[1];
    const float* V     = (const float*)d_in[2];
    const float* W_Q   = (const float*)d_in[3];
    const float* W_K   = (const float*)d_in[4];
    const float* W_V   = (const float*)d_in[5];
    const float* W_O   = (const float*)d_in[6];
    const float* gamma = (const float*)d_in[7];
    const float* beta  = (const float*)d_in[8];
    float* out = (float*)d_out;

    float *qh, *kh, *vh, *ctx;
    cudaGetSymbolAddress((void**)&qh,  g_Qh);
    cudaGetSymbolAddress((void**)&kh,  g_Kh);
    cudaGetSymbolAddress((void**)&vh,  g_Vh);
    cudaGetSymbolAddress((void**)&ctx, g_ctx);

    const int attn_smem = ATTN_SMEM_FLOATS * (int)sizeof(float);  // 51200 B
    cudaFuncSetAttribute(attn_kernel, cudaFuncAttributeMaxDynamicSharedMemorySize,
                         attn_smem);

    const dim3 gb(NDM / 64, NM / 64);   // (16, 128)
    gemm64<true><<<gb, 256>>>(Q, W_Q, qh);
    gemm64<true><<<gb, 256>>>(K, W_K, kh);
    gemm64<true><<<gb, 256>>>(V, W_V, vh);
    attn_kernel<<<dim3(NS / 64, NB * NH), 256, attn_smem>>>(qh, kh, vh, ctx);
    gemm64<false><<<gb, 256>>>(ctx, W_O, out);
    ln_kernel<<<NM, 256>>>(Q, gamma, beta, out);
}

// round 2
// speedup vs baseline: 3.4735x; 3.4735x over previous
#include <cuda_runtime.h>
#include <cstdint>

// Problem constants
#define NB   4
#define NS   2048
#define NDM  1024
#define NH   16
#define NM   (NB * NS)      // 8192 rows

// ---------------------------------------------------------------------------
// Device scratch
// ---------------------------------------------------------------------------
__device__ float g_Qh[NB * NH * NS * 64];   // [B,H,S,64]
__device__ float g_Kh[NB * NH * NS * 64];
__device__ float g_Vh[NB * NH * NS * 64];
__device__ float g_ctx[NM * NDM];           // [B*S, H*Dv]

// ---------------------------------------------------------------------------
// tf32 helpers
// ---------------------------------------------------------------------------
__device__ __forceinline__ uint32_t f2tf(float x) {
    uint32_t r;
    asm("cvt.rna.tf32.f32 %0, %1;" : "=r"(r) : "f"(x));
    return r;
}

__device__ __forceinline__ void mma_tf32(float c[4], const uint32_t a[4],
                                         uint32_t b0, uint32_t b1) {
    asm volatile(
        "mma.sync.aligned.m16n8k8.row.col.f32.tf32.tf32.f32 "
        "{%0,%1,%2,%3}, {%4,%5,%6,%7}, {%8,%9}, {%0,%1,%2,%3};"
        : "+f"(c[0]), "+f"(c[1]), "+f"(c[2]), "+f"(c[3])
        : "r"(a[0]), "r"(a[1]), "r"(a[2]), "r"(a[3]), "r"(b0), "r"(b1));
}

// ---------------------------------------------------------------------------
// tf32 tensor-core GEMM: C[8192,1024] = A[8192,1024] @ W[1024,1024]
// BM=128, BN=128, BK=32; 8 warps, warp tile 32x64.
// As: [m][k] pad 36 (banks 4*lr+lq), Bs: [k][n] pad 136 (banks 8*lq+lr).
// ---------------------------------------------------------------------------
#define GAP 36
#define GBP 136

template <bool HEADS>
__global__ __launch_bounds__(256) void gemm_tc(const float* __restrict__ A,
                                               const float* __restrict__ W,
                                               float* __restrict__ C) {
    __shared__ uint32_t As[128 * GAP];
    __shared__ uint32_t Bs[32 * GBP];

    const int tid  = threadIdx.x;
    const int lane = tid & 31;
    const int wid  = tid >> 5;
    const int lr   = lane >> 2;
    const int lq   = lane & 3;
    const int wm0  = (wid & 3) * 32;
    const int wn0  = (wid >> 2) * 64;
    const int m0   = blockIdx.y * 128;
    const int n0   = blockIdx.x * 128;

    // gmem load mapping
    const int arow = tid >> 3;           // 0..31 (+32i)
    const int acol = (tid & 7) << 2;     // 0..28
    const int bk   = tid >> 5;           // 0..7 (+8i)
    const int bn   = (tid & 31) << 2;    // 0..124

    const float* Ap = A + (size_t)(m0 + arow) * NDM + acol;
    const float* Bp = W + (size_t)bk * NDM + n0 + bn;

    float4 ra[4], rb[4];
#pragma unroll
    for (int i = 0; i < 4; i++) {
        ra[i] = *(const float4*)(Ap + (size_t)(32 * i) * NDM);
        rb[i] = *(const float4*)(Bp + (size_t)(8 * i) * NDM);
    }

    float acc[2][8][4];
#pragma unroll
    for (int mi = 0; mi < 2; mi++)
#pragma unroll
        for (int nt = 0; nt < 8; nt++)
#pragma unroll
            for (int v = 0; v < 4; v++) acc[mi][nt][v] = 0.f;

    for (int k0 = 0; k0 < NDM; k0 += 32) {
        __syncthreads();
#pragma unroll
        for (int i = 0; i < 4; i++) {
            const int r = arow + 32 * i;
            As[r * GAP + acol + 0] = f2tf(ra[i].x);
            As[r * GAP + acol + 1] = f2tf(ra[i].y);
            As[r * GAP + acol + 2] = f2tf(ra[i].z);
            As[r * GAP + acol + 3] = f2tf(ra[i].w);
            const int kR = bk + 8 * i;
            uint4 bb = make_uint4(f2tf(rb[i].x), f2tf(rb[i].y),
                                  f2tf(rb[i].z), f2tf(rb[i].w));
            *(uint4*)&Bs[kR * GBP + bn] = bb;
        }
        __syncthreads();

        if (k0 + 32 < NDM) {
#pragma unroll
            for (int i = 0; i < 4; i++) {
                ra[i] = *(const float4*)(Ap + (size_t)(32 * i) * NDM + k0 + 32);
                rb[i] = *(const float4*)(Bp + (size_t)(k0 + 32 + 8 * i) * NDM);
            }
        }

#pragma unroll
        for (int kk = 0; kk < 32; kk += 8) {
            uint32_t a[2][4];
#pragma unroll
            for (int mi = 0; mi < 2; mi++) {
                const uint32_t* base = &As[(wm0 + mi * 16 + lr) * GAP + kk + lq];
                a[mi][0] = base[0];
                a[mi][1] = base[8 * GAP];
                a[mi][2] = base[4];
                a[mi][3] = base[8 * GAP + 4];
            }
#pragma unroll
            for (int nt = 0; nt < 8; nt++) {
                const uint32_t b0 = Bs[(kk + lq) * GBP + wn0 + nt * 8 + lr];
                const uint32_t b1 = Bs[(kk + 4 + lq) * GBP + wn0 + nt * 8 + lr];
                mma_tf32(acc[0][nt], a[0], b0, b1);
                mma_tf32(acc[1][nt], a[1], b0, b1);
            }
        }
    }

    // Epilogue
#pragma unroll
    for (int mi = 0; mi < 2; mi++) {
        const int row0 = m0 + wm0 + mi * 16 + lr;
#pragma unroll
        for (int nt = 0; nt < 8; nt++) {
            const int col = n0 + wn0 + nt * 8 + 2 * lq;
            float2 v0 = make_float2(acc[mi][nt][0], acc[mi][nt][1]);
            float2 v1 = make_float2(acc[mi][nt][2], acc[mi][nt][3]);
            if (HEADS) {
                const int h = col >> 6, d = col & 63;
                const int b0i = row0 >> 11, s0 = row0 & 2047;
                *(float2*)&C[(size_t)(((b0i * NH + h) * NS + s0)) * 64 + d] = v0;
                const int row1 = row0 + 8;
                const int b1i = row1 >> 11, s1 = row1 & 2047;
                *(float2*)&C[(size_t)(((b1i * NH + h) * NS + s1)) * 64 + d] = v1;
            } else {
                *(float2*)&C[(size_t)row0 * NDM + col] = v0;
                *(float2*)&C[(size_t)(row0 + 8) * NDM + col] = v1;
            }
        }
    }
}

// ---------------------------------------------------------------------------
// Flash attention, causal, tf32 tensor cores.
// Q tile 128, K tile 64. 8 warps; warp w owns q-rows [16w,16w+16).
// Qs/Ks/Ps stride 68, Vs stride 72 (fragment LDS conflict-free).
// ---------------------------------------------------------------------------
#define AP 68
#define VP 72
#define ATTN_SMEM_BYTES ((128 * AP + 64 * AP + 128 * AP + 64 * VP) * 4)

__global__ __launch_bounds__(256) void attn_tc(const float* __restrict__ Qh,
                                               const float* __restrict__ Kh,
                                               const float* __restrict__ Vh,
                                               float* __restrict__ ctx) {
    extern __shared__ uint32_t sm[];
    uint32_t* Qs = sm;                   // [128][68]
    uint32_t* Ks = Qs + 128 * AP;        // [64][68]
    uint32_t* Ps = Ks + 64 * AP;         // [128][68]
    uint32_t* Vs = Ps + 128 * AP;        // [64][72]

    const int tid  = threadIdx.x;
    const int lane = tid & 31;
    const int wid  = tid >> 5;
    const int lr   = lane >> 2;
    const int lq   = lane & 3;

    const int qt = gridDim.x - 1 - blockIdx.x;   // heavy tiles first
    const int bh = blockIdx.y;

    const float* Qb = Qh + (size_t)bh * NS * 64;
    const float* Kb = Kh + (size_t)bh * NS * 64;
    const float* Vb = Vh + (size_t)bh * NS * 64;

    // Load Q tile (128 x 64), convert to tf32
    {
        const int r0 = tid >> 4;           // 0..15 (+16i)
        const int c  = (tid & 15) << 2;
#pragma unroll
        for (int i = 0; i < 8; i++) {
            const int r = r0 + 16 * i;
            float4 q = *(const float4*)(Qb + (size_t)(qt * 128 + r) * 64 + c);
            Qs[r * AP + c + 0] = f2tf(q.x);
            Qs[r * AP + c + 1] = f2tf(q.y);
            Qs[r * AP + c + 2] = f2tf(q.z);
            Qs[r * AP + c + 3] = f2tf(q.w);
        }
    }

    float o[8][4];
#pragma unroll
    for (int nt = 0; nt < 8; nt++)
#pragma unroll
        for (int v = 0; v < 4; v++) o[nt][v] = 0.f;
    float mrow0 = -1e30f, mrow1 = -1e30f, lsum0 = 0.f, lsum1 = 0.f;

    const int qrow0 = qt * 128 + wid * 16 + lr;
    const int qrow1 = qrow0 + 8;
    const int ktmax = 2 * qt + 1;

    for (int kt = 0; kt <= ktmax; kt++) {
        __syncthreads();   // prior S (Ks) and PV (Vs) reads complete
        {
            const int r0 = tid >> 4;
            const int c  = (tid & 15) << 2;
#pragma unroll
            for (int i = 0; i < 4; i++) {
                const int r = r0 + 16 * i;
                float4 kv = *(const float4*)(Kb + (size_t)(kt * 64 + r) * 64 + c);
                float4 vv = *(const float4*)(Vb + (size_t)(kt * 64 + r) * 64 + c);
                Ks[r * AP + c + 0] = f2tf(kv.x);
                Ks[r * AP + c + 1] = f2tf(kv.y);
                Ks[r * AP + c + 2] = f2tf(kv.z);
                Ks[r * AP + c + 3] = f2tf(kv.w);
                Vs[r * VP + c + 0] = f2tf(vv.x);
                Vs[r * VP + c + 1] = f2tf(vv.y);
                Vs[r * VP + c + 2] = f2tf(vv.z);
                Vs[r * VP + c + 3] = f2tf(vv.w);
            }
        }
        __syncthreads();

        // ---- S = Q K^T ----
        float s[8][4];
#pragma unroll
        for (int nt = 0; nt < 8; nt++)
#pragma unroll
            for (int v = 0; v < 4; v++) s[nt][v] = 0.f;

#pragma unroll
        for (int kk = 0; kk < 64; kk += 8) {
            uint32_t a[4];
            const uint32_t* qb = &Qs[(wid * 16 + lr) * AP + kk + lq];
            a[0] = qb[0];
            a[1] = qb[8 * AP];
            a[2] = qb[4];
            a[3] = qb[8 * AP + 4];
#pragma unroll
            for (int nt = 0; nt < 8; nt++) {
                const uint32_t b0 = Ks[(nt * 8 + lr) * AP + kk + lq];
                const uint32_t b1 = Ks[(nt * 8 + lr) * AP + kk + 4 + lq];
                mma_tf32(s[nt], a, b0, b1);
            }
        }

        // scale + causal mask
        const bool diag = (kt >= 2 * qt);
#pragma unroll
        for (int nt = 0; nt < 8; nt++) {
            const int col = kt * 64 + nt * 8 + 2 * lq;
            s[nt][0] *= 0.125f;
            s[nt][1] *= 0.125f;
            s[nt][2] *= 0.125f;
            s[nt][3] *= 0.125f;
            if (diag) {
                if (col     > qrow0) s[nt][0] = -1e30f;
                if (col + 1 > qrow0) s[nt][1] = -1e30f;
                if (col     > qrow1) s[nt][2] = -1e30f;
                if (col + 1 > qrow1) s[nt][3] = -1e30f;
            }
        }

        // ---- online softmax (rows lr and lr+8; reduce over quad lanes) ----
        float mx0 = -1e30f, mx1 = -1e30f;
#pragma unroll
        for (int nt = 0; nt < 8; nt++) {
            mx0 = fmaxf(mx0, fmaxf(s[nt][0], s[nt][1]));
            mx1 = fmaxf(mx1, fmaxf(s[nt][2], s[nt][3]));
        }
        mx0 = fmaxf(mx0, __shfl_xor_sync(0xffffffffu, mx0, 1));
        mx0 = fmaxf(mx0, __shfl_xor_sync(0xffffffffu, mx0, 2));
        mx1 = fmaxf(mx1, __shfl_xor_sync(0xffffffffu, mx1, 1));
        mx1 = fmaxf(mx1, __shfl_xor_sync(0xffffffffu, mx1, 2));

        const float mn0 = fmaxf(mrow0, mx0);
        const float mn1 = fmaxf(mrow1, mx1);
        const float corr0 = __expf(mrow0 - mn0);
        const float corr1 = __expf(mrow1 - mn1);

        float rs0 = 0.f, rs1 = 0.f;
#pragma unroll
        for (int nt = 0; nt < 8; nt++) {
            s[nt][0] = __expf(s[nt][0] - mn0);
            s[nt][1] = __expf(s[nt][1] - mn0);
            s[nt][2] = __expf(s[nt][2] - mn1);
            s[nt][3] = __expf(s[nt][3] - mn1);
            rs0 += s[nt][0] + s[nt][1];
            rs1 += s[nt][2] + s[nt][3];
        }
        rs0 += __shfl_xor_sync(0xffffffffu, rs0, 1);
        rs0 += __shfl_xor_sync(0xffffffffu, rs0, 2);
        rs1 += __shfl_xor_sync(0xffffffffu, rs1, 1);
        rs1 += __shfl_xor_sync(0xffffffffu, rs1, 2);

        lsum0 = lsum0 * corr0 + rs0;
        lsum1 = lsum1 * corr1 + rs1;
        mrow0 = mn0;
        mrow1 = mn1;
#pragma unroll
        for (int nt = 0; nt < 8; nt++) {
            o[nt][0] *= corr0;
            o[nt][1] *= corr0;
            o[nt][2] *= corr1;
            o[nt][3] *= corr1;
        }

        // ---- store P (warp-private rows) ----
#pragma unroll
        for (int nt = 0; nt < 8; nt++) {
            const int kcol = nt * 8 + 2 * lq;
            *(uint2*)&Ps[(wid * 16 + lr) * AP + kcol] =
                make_uint2(f2tf(s[nt][0]), f2tf(s[nt][1]));
            *(uint2*)&Ps[(wid * 16 + lr + 8) * AP + kcol] =
                make_uint2(f2tf(s[nt][2]), f2tf(s[nt][3]));
        }
        __syncwarp();

        // ---- O += P V ----
#pragma unroll
        for (int kk = 0; kk < 64; kk += 8) {
            uint32_t a[4];
            const uint32_t* pb = &Ps[(wid * 16 + lr) * AP + kk + lq];
            a[0] = pb[0];
            a[1] = pb[8 * AP];
            a[2] = pb[4];
            a[3] = pb[8 * AP + 4];
#pragma unroll
            for (int nt = 0; nt < 8; nt++) {
                const uint32_t b0 = Vs[(kk + lq) * VP + nt * 8 + lr];
                const uint32_t b1 = Vs[(kk + 4 + lq) * VP + nt * 8 + lr];
                mma_tf32(o[nt], a, b0, b1);
            }
        }
    }

    // ---- write ctx [B*S, H*64] ----
    const int b = bh >> 4;
    const int h = bh & 15;
    const float inv0 = 1.f / lsum0;
    const float inv1 = 1.f / lsum1;
    const int srow = qt * 128 + wid * 16 + lr;
#pragma unroll
    for (int nt = 0; nt < 8; nt++) {
        const int d = nt * 8 + 2 * lq;
        *(float2*)&ctx[(size_t)(b * NS + srow) * NDM + h * 64 + d] =
            make_float2(o[nt][0] * inv0, o[nt][1] * inv0);
        *(float2*)&ctx[(size_t)(b * NS + srow + 8) * NDM + h * 64 + d] =
            make_float2(o[nt][2] * inv1, o[nt][3] * inv1);
    }
}

// ---------------------------------------------------------------------------
// Fused residual + LayerNorm (in-place on out)
// ---------------------------------------------------------------------------
__global__ __launch_bounds__(256) void ln_kernel(const float* __restrict__ Qin,
                                                 const float* __restrict__ gamma,
                                                 const float* __restrict__ beta,
                                                 float* __restrict__ out) {
    __shared__ float rs[8], rq[8], fin[2];
    const int row = blockIdx.x;
    const int tid = threadIdx.x;
    const int c   = tid << 2;

    float4 o4 = *(const float4*)(out + (size_t)row * NDM + c);
    float4 q4 = *(const float4*)(Qin + (size_t)row * NDM + c);
    const float x0 = o4.x + q4.x, x1 = o4.y + q4.y, x2 = o4.z + q4.z, x3 = o4.w + q4.w;
    float s  = x0 + x1 + x2 + x3;
    float sq = x0 * x0 + x1 * x1 + x2 * x2 + x3 * x3;
#pragma unroll
    for (int off = 16; off; off >>= 1) {
        s  += __shfl_xor_sync(0xffffffffu, s, off);
        sq += __shfl_xor_sync(0xffffffffu, sq, off);
    }
    const int wid = tid >> 5, lane = tid & 31;
    if (lane == 0) { rs[wid] = s; rq[wid] = sq; }
    __syncthreads();
    if (tid == 0) {
        float a = 0.f, b2 = 0.f;
#pragma unroll
        for (int i = 0; i < 8; i++) { a += rs[i]; b2 += rq[i]; }
        fin[0] = a;
        fin[1] = b2;
    }
    __syncthreads();
    const float mu   = fin[0] * (1.0f / NDM);
    const float var  = fin[1] * (1.0f / NDM) - mu * mu;
    const float rstd = rsqrtf(var + 1e-5f);

    float4 g4 = *(const float4*)(gamma + c);
    float4 b4 = *(const float4*)(beta + c);
    float4 r;
    r.x = (x0 - mu) * rstd * g4.x + b4.x;
    r.y = (x1 - mu) * rstd * g4.y + b4.y;
    r.z = (x2 - mu) * rstd * g4.z + b4.z;
    r.w = (x3 - mu) * rstd * g4.w + b4.w;
    *(float4*)(out + (size_t)row * NDM + c) = r;
}

// ---------------------------------------------------------------------------
// Launch
// ---------------------------------------------------------------------------
extern "C" void kernel_launch(void* const* d_in, const int* in_sizes, int n_in,
                              void* d_out, int out_size) {
    const float* Q     = (const float*)d_in[0];
    const float* K     = (const float*)d_in[1];
    const float* V     = (const float*)d_in[2];
    const float* W_Q   = (const float*)d_in[3];
    const float* W_K   = (const float*)d_in[4];
    const float* W_V   = (const float*)d_in[5];
    const float* W_O   = (const float*)d_in[6];
    const float* gamma = (const float*)d_in[7];
    const float* beta  = (const float*)d_in[8];
    float* out = (float*)d_out;

    float *qh, *kh, *vh, *ctx;
    cudaGetSymbolAddress((void**)&qh,  g_Qh);
    cudaGetSymbolAddress((void**)&kh,  g_Kh);
    cudaGetSymbolAddress((void**)&vh,  g_Vh);
    cudaGetSymbolAddress((void**)&ctx, g_ctx);

    cudaFuncSetAttribute(attn_tc, cudaFuncAttributeMaxDynamicSharedMemorySize,
                         ATTN_SMEM_BYTES);

    const dim3 gb(NDM / 128, NM / 128);   // (8, 64)
    gemm_tc<true><<<gb, 256>>>(Q, W_Q, qh);
    gemm_tc<true><<<gb, 256>>>(K, W_K, kh);
    gemm_tc<true><<<gb, 256>>>(V, W_V, vh);
    attn_tc<<<dim3(NS / 128, NB * NH), 256, ATTN_SMEM_BYTES>>>(qh, kh, vh, ctx);
    gemm_tc<false><<<gb, 256>>>(ctx, W_O, out);
    ln_kernel<<<NM, 256>>>(Q, gamma, beta, out);
}

// round 4
// speedup vs baseline: 3.8560x; 1.1101x over previous
#include <cuda_runtime.h>
#include <cuda_bf16.h>
#include <cstdint>

// Problem constants
#define NB   4
#define NS   2048
#define NDM  1024
#define NH   16
#define NM   (NB * NS)      // 8192 rows

// ---------------------------------------------------------------------------
// Device scratch
// ---------------------------------------------------------------------------
__device__ float g_Qh[NB * NH * NS * 64];        // tf32-rounded fp32 heads [B,H,S,64]
__device__ float g_Kh[NB * NH * NS * 64];
__device__ float g_Vh[NB * NH * NS * 64];
__device__ __nv_bfloat16 g_ctxb[NM * NDM];       // bf16 ctx [B*S, H*Dv]

__device__ __nv_bfloat16 g_Qb[NM * NDM];         // bf16 activations [m][k]
__device__ __nv_bfloat16 g_Kb[NM * NDM];
__device__ __nv_bfloat16 g_Vb[NM * NDM];
__device__ __nv_bfloat16 g_WTq[NDM * NDM];       // bf16 W^T [n][k]
__device__ __nv_bfloat16 g_WTk[NDM * NDM];
__device__ __nv_bfloat16 g_WTv[NDM * NDM];
__device__ __nv_bfloat16 g_WTo[NDM * NDM];

// ---------------------------------------------------------------------------
// mma helpers
// ---------------------------------------------------------------------------
__device__ __forceinline__ uint32_t f2tf(float x) {
    uint32_t r;
    asm("cvt.rna.tf32.f32 %0, %1;" : "=r"(r) : "f"(x));
    return r;
}

__device__ __forceinline__ void mma_tf32(float c[4], const uint32_t a[4],
                                         uint32_t b0, uint32_t b1) {
    asm volatile(
        "mma.sync.aligned.m16n8k8.row.col.f32.tf32.tf32.f32 "
        "{%0,%1,%2,%3}, {%4,%5,%6,%7}, {%8,%9}, {%0,%1,%2,%3};"
        : "+f"(c[0]), "+f"(c[1]), "+f"(c[2]), "+f"(c[3])
        : "r"(a[0]), "r"(a[1]), "r"(a[2]), "r"(a[3]), "r"(b0), "r"(b1));
}

__device__ __forceinline__ void mma_bf16(float c[4], const uint32_t a[4],
                                         uint32_t b0, uint32_t b1) {
    asm volatile(
        "mma.sync.aligned.m16n8k16.row.col.f32.bf16.bf16.f32 "
        "{%0,%1,%2,%3}, {%4,%5,%6,%7}, {%8,%9}, {%0,%1,%2,%3};"
        : "+f"(c[0]), "+f"(c[1]), "+f"(c[2]), "+f"(c[3])
        : "r"(a[0]), "r"(a[1]), "r"(a[2]), "r"(a[3]), "r"(b0), "r"(b1));
}

// ---------------------------------------------------------------------------
// Conversion kernels
// ---------------------------------------------------------------------------
__global__ __launch_bounds__(256) void f2b_kernel(const float* __restrict__ in,
                                                  __nv_bfloat16* __restrict__ out) {
    const int i = (blockIdx.x * 256 + threadIdx.x) * 4;
    float4 v = *(const float4*)(in + i);
    __nv_bfloat162 a = __floats2bfloat162_rn(v.x, v.y);
    __nv_bfloat162 b = __floats2bfloat162_rn(v.z, v.w);
    uint2 u;
    u.x = *(uint32_t*)&a;
    u.y = *(uint32_t*)&b;
    *(uint2*)(out + i) = u;
}

// W [k][n] fp32 -> WT [n][k] bf16 (tiled transpose)
__global__ __launch_bounds__(256) void wtrans_kernel(const float* __restrict__ W,
                                                     __nv_bfloat16* __restrict__ WT) {
    __shared__ float t[32][33];
    const int tx = threadIdx.x & 31;
    const int ty = threadIdx.x >> 5;
    const int bn = blockIdx.x * 32;
    const int bk = blockIdx.y * 32;
#pragma unroll
    for (int i = 0; i < 4; i++)
        t[ty + 8 * i][tx] = W[(size_t)(bk + ty + 8 * i) * NDM + bn + tx];
    __syncthreads();
#pragma unroll
    for (int i = 0; i < 4; i++)
        WT[(size_t)(bn + ty + 8 * i) * NDM + bk + tx] =
            __float2bfloat16(t[tx][ty + 8 * i]);
}

// ---------------------------------------------------------------------------
// bf16 mma.sync GEMM: C[8192,1024] = A_bf[m][k] @ WT_bf[n][k]^T
// BM=128, BN=128, BK=32 (2 k16 steps); 8 warps, warp tile 32x64.
// Smem tiles uint32[128][20] (40 bf16 stride) - fragment LDS conflict-free.
// HEADS epilogue: tf32-round and write [B,H,S,64]; else fp32 [m][1024].
// ---------------------------------------------------------------------------
#define GW 20   // 32-bit words per smem row

template <bool HEADS>
__global__ __launch_bounds__(256) void gemm_bf(const __nv_bfloat16* __restrict__ A,
                                               const __nv_bfloat16* __restrict__ BT,
                                               float* __restrict__ C) {
    __shared__ uint32_t As[128 * GW];
    __shared__ uint32_t Bs[128 * GW];

    const int tid  = threadIdx.x;
    const int lane = tid & 31;
    const int wid  = tid >> 5;
    const int lr   = lane >> 2;
    const int lq   = lane & 3;
    const int wm0  = (wid & 3) * 32;
    const int wn0  = (wid >> 2) * 64;
    const int m0   = blockIdx.y * 128;
    const int n0   = blockIdx.x * 128;

    // gmem load mapping: task i (0/1): row r = (tid>>2)+64*i, 16B piece cu = tid&3
    const int r0 = tid >> 2;
    const int cu = tid & 3;
    const uint8_t* Ag = (const uint8_t*)A + (size_t)m0 * 2048 + cu * 16;
    const uint8_t* Bg = (const uint8_t*)BT + (size_t)n0 * 2048 + cu * 16;

    uint4 ra[2], rb[2];
#pragma unroll
    for (int i = 0; i < 2; i++) {
        ra[i] = *(const uint4*)(Ag + (size_t)(r0 + 64 * i) * 2048);
        rb[i] = *(const uint4*)(Bg + (size_t)(r0 + 64 * i) * 2048);
    }

    float acc[2][8][4];
#pragma unroll
    for (int mi = 0; mi < 2; mi++)
#pragma unroll
        for (int nt = 0; nt < 8; nt++)
#pragma unroll
            for (int v = 0; v < 4; v++) acc[mi][nt][v] = 0.f;

    for (int c = 0; c < 32; c++) {          // 32 chunks of BK=32 bf16 (64 B)
        __syncthreads();
#pragma unroll
        for (int i = 0; i < 2; i++) {
            const int off = (r0 + 64 * i) * GW + cu * 4;
            *(uint4*)&As[off] = ra[i];
            *(uint4*)&Bs[off] = rb[i];
        }
        __syncthreads();

        if (c + 1 < 32) {
            const size_t koff = (size_t)(c + 1) * 64;
#pragma unroll
            for (int i = 0; i < 2; i++) {
                ra[i] = *(const uint4*)(Ag + (size_t)(r0 + 64 * i) * 2048 + koff);
                rb[i] = *(const uint4*)(Bg + (size_t)(r0 + 64 * i) * 2048 + koff);
            }
        }

#pragma unroll
        for (int s = 0; s < 2; s++) {       // two k16 steps
            uint32_t a[2][4];
#pragma unroll
            for (int mi = 0; mi < 2; mi++) {
                const uint32_t* base = &As[(wm0 + mi * 16 + lr) * GW + s * 8 + lq];
                a[mi][0] = base[0];
                a[mi][1] = base[8 * GW];
                a[mi][2] = base[4];
                a[mi][3] = base[8 * GW + 4];
            }
#pragma unroll
            for (int nt = 0; nt < 8; nt++) {
                const uint32_t* bb = &Bs[(wn0 + nt * 8 + lr) * GW + s * 8 + lq];
                const uint32_t b0 = bb[0];
                const uint32_t b1 = bb[4];
                mma_bf16(acc[0][nt], a[0], b0, b1);
                mma_bf16(acc[1][nt], a[1], b0, b1);
            }
        }
    }

    // Epilogue
#pragma unroll
    for (int mi = 0; mi < 2; mi++) {
        const int row0 = m0 + wm0 + mi * 16 + lr;
#pragma unroll
        for (int nt = 0; nt < 8; nt++) {
            const int col = wn0 + nt * 8 + 2 * lq;   // 0..127 within block
            if (HEADS) {
                // tf32-round so attention can bit-copy into smem
                float2 v0, v1;
                v0.x = __uint_as_float(f2tf(acc[mi][nt][0]));
                v0.y = __uint_as_float(f2tf(acc[mi][nt][1]));
                v1.x = __uint_as_float(f2tf(acc[mi][nt][2]));
                v1.y = __uint_as_float(f2tf(acc[mi][nt][3]));
                const int gcol = n0 + col;
                const int h = gcol >> 6, d = gcol & 63;
                const int b0i = row0 >> 11, s0 = row0 & 2047;
                *(float2*)&C[(size_t)((b0i * NH + h) * NS + s0) * 64 + d] = v0;
                const int row1 = row0 + 8;
                const int b1i = row1 >> 11, s1 = row1 & 2047;
                *(float2*)&C[(size_t)((b1i * NH + h) * NS + s1) * 64 + d] = v1;
            } else {
                *(float2*)&C[(size_t)row0 * NDM + n0 + col] =
                    make_float2(acc[mi][nt][0], acc[mi][nt][1]);
                *(float2*)&C[(size_t)(row0 + 8) * NDM + n0 + col] =
                    make_float2(acc[mi][nt][2], acc[mi][nt][3]);
            }
        }
    }
}

// ---------------------------------------------------------------------------
// Flash attention, causal, tf32 mma.sync.
// Q tile 128, K tile 64. 8 warps; warp w owns q-rows [16w,16w+16).
// Inputs are tf32-pre-rounded fp32 -> smem fill is a bit copy.
// Output written directly as bf16 [B*S, H*64].
// ---------------------------------------------------------------------------
#define AP 68
#define VP 72
#define ATTN_SMEM_BYTES ((128 * AP + 64 * AP + 128 * AP + 64 * VP) * 4)

__global__ __launch_bounds__(256) void attn_tc(const float* __restrict__ Qh,
                                               const float* __restrict__ Kh,
                                               const float* __restrict__ Vh,
                                               __nv_bfloat16* __restrict__ ctx) {
    extern __shared__ uint32_t sm[];
    uint32_t* Qs = sm;
    uint32_t* Ks = Qs + 128 * AP;
    uint32_t* Ps = Ks + 64 * AP;
    uint32_t* Vs = Ps + 128 * AP;

    const int tid  = threadIdx.x;
    const int lane = tid & 31;
    const int wid  = tid >> 5;
    const int lr   = lane >> 2;
    const int lq   = lane & 3;

    const int qt = gridDim.x - 1 - blockIdx.x;   // heavy tiles first
    const int bh = blockIdx.y;

    const float* Qb = Qh + (size_t)bh * NS * 64;
    const float* Kb = Kh + (size_t)bh * NS * 64;
    const float* Vb = Vh + (size_t)bh * NS * 64;

    {
        const int r0 = tid >> 4;
        const int c  = (tid & 15) << 2;
#pragma unroll
        for (int i = 0; i < 8; i++) {
            const int r = r0 + 16 * i;
            uint4 q = *(const uint4*)(Qb + (size_t)(qt * 128 + r) * 64 + c);
            Qs[r * AP + c + 0] = q.x;
            Qs[r * AP + c + 1] = q.y;
            Qs[r * AP + c + 2] = q.z;
            Qs[r * AP + c + 3] = q.w;
        }
    }

    float o[8][4];
#pragma unroll
    for (int nt = 0; nt < 8; nt++)
#pragma unroll
        for (int v = 0; v < 4; v++) o[nt][v] = 0.f;
    float mrow0 = -1e30f, mrow1 = -1e30f, lsum0 = 0.f, lsum1 = 0.f;

    const int qrow0 = qt * 128 + wid * 16 + lr;
    const int qrow1 = qrow0 + 8;
    const int ktmax = 2 * qt + 1;

    for (int kt = 0; kt <= ktmax; kt++) {
        __syncthreads();
        {
            const int r0 = tid >> 4;
            const int c  = (tid & 15) << 2;
#pragma unroll
            for (int i = 0; i < 4; i++) {
                const int r = r0 + 16 * i;
                uint4 kv = *(const uint4*)(Kb + (size_t)(kt * 64 + r) * 64 + c);
                uint4 vv = *(const uint4*)(Vb + (size_t)(kt * 64 + r) * 64 + c);
                Ks[r * AP + c + 0] = kv.x;
                Ks[r * AP + c + 1] = kv.y;
                Ks[r * AP + c + 2] = kv.z;
                Ks[r * AP + c + 3] = kv.w;
                Vs[r * VP + c + 0] = vv.x;
                Vs[r * VP + c + 1] = vv.y;
                Vs[r * VP + c + 2] = vv.z;
                Vs[r * VP + c + 3] = vv.w;
            }
        }
        __syncthreads();

        float s[8][4];
#pragma unroll
        for (int nt = 0; nt < 8; nt++)
#pragma unroll
            for (int v = 0; v < 4; v++) s[nt][v] = 0.f;

#pragma unroll
        for (int kk = 0; kk < 64; kk += 8) {
            uint32_t a[4];
            const uint32_t* qb = &Qs[(wid * 16 + lr) * AP + kk + lq];
            a[0] = qb[0];
            a[1] = qb[8 * AP];
            a[2] = qb[4];
            a[3] = qb[8 * AP + 4];
#pragma unroll
            for (int nt = 0; nt < 8; nt++) {
                const uint32_t b0 = Ks[(nt * 8 + lr) * AP + kk + lq];
                const uint32_t b1 = Ks[(nt * 8 + lr) * AP + kk + 4 + lq];
                mma_tf32(s[nt], a, b0, b1);
            }
        }

        const bool diag = (kt >= 2 * qt);
#pragma unroll
        for (int nt = 0; nt < 8; nt++) {
            const int col = kt * 64 + nt * 8 + 2 * lq;
            s[nt][0] *= 0.125f;
            s[nt][1] *= 0.125f;
            s[nt][2] *= 0.125f;
            s[nt][3] *= 0.125f;
            if (diag) {
                if (col     > qrow0) s[nt][0] = -1e30f;
                if (col + 1 > qrow0) s[nt][1] = -1e30f;
                if (col     > qrow1) s[nt][2] = -1e30f;
                if (col + 1 > qrow1) s[nt][3] = -1e30f;
            }
        }

        float mx0 = -1e30f, mx1 = -1e30f;
#pragma unroll
        for (int nt = 0; nt < 8; nt++) {
            mx0 = fmaxf(mx0, fmaxf(s[nt][0], s[nt][1]));
            mx1 = fmaxf(mx1, fmaxf(s[nt][2], s[nt][3]));
        }
        mx0 = fmaxf(mx0, __shfl_xor_sync(0xffffffffu, mx0, 1));
        mx0 = fmaxf(mx0, __shfl_xor_sync(0xffffffffu, mx0, 2));
        mx1 = fmaxf(mx1, __shfl_xor_sync(0xffffffffu, mx1, 1));
        mx1 = fmaxf(mx1, __shfl_xor_sync(0xffffffffu, mx1, 2));

        const float mn0 = fmaxf(mrow0, mx0);
        const float mn1 = fmaxf(mrow1, mx1);
        const float corr0 = __expf(mrow0 - mn0);
        const float corr1 = __expf(mrow1 - mn1);

        float rs0 = 0.f, rs1 = 0.f;
#pragma unroll
        for (int nt = 0; nt < 8; nt++) {
            s[nt][0] = __expf(s[nt][0] - mn0);
            s[nt][1] = __expf(s[nt][1] - mn0);
            s[nt][2] = __expf(s[nt][2] - mn1);
            s[nt][3] = __expf(s[nt][3] - mn1);
            rs0 += s[nt][0] + s[nt][1];
            rs1 += s[nt][2] + s[nt][3];
        }
        rs0 += __shfl_xor_sync(0xffffffffu, rs0, 1);
        rs0 += __shfl_xor_sync(0xffffffffu, rs0, 2);
        rs1 += __shfl_xor_sync(0xffffffffu, rs1, 1);
        rs1 += __shfl_xor_sync(0xffffffffu, rs1, 2);

        lsum0 = lsum0 * corr0 + rs0;
        lsum1 = lsum1 * corr1 + rs1;
        mrow0 = mn0;
        mrow1 = mn1;
#pragma unroll
        for (int nt = 0; nt < 8; nt++) {
            o[nt][0] *= corr0;
            o[nt][1] *= corr0;
            o[nt][2] *= corr1;
            o[nt][3] *= corr1;
        }

#pragma unroll
        for (int nt = 0; nt < 8; nt++) {
            const int kcol = nt * 8 + 2 * lq;
            *(uint2*)&Ps[(wid * 16 + lr) * AP + kcol] =
                make_uint2(f2tf(s[nt][0]), f2tf(s[nt][1]));
            *(uint2*)&Ps[(wid * 16 + lr + 8) * AP + kcol] =
                make_uint2(f2tf(s[nt][2]), f2tf(s[nt][3]));
        }
        __syncwarp();

#pragma unroll
        for (int kk = 0; kk < 64; kk += 8) {
            uint32_t a[4];
            const uint32_t* pb = &Ps[(wid * 16 + lr) * AP + kk + lq];
            a[0] = pb[0];
            a[1] = pb[8 * AP];
            a[2] = pb[4];
            a[3] = pb[8 * AP + 4];
#pragma unroll
            for (int nt = 0; nt < 8; nt++) {
                const uint32_t b0 = Vs[(kk + lq) * VP + nt * 8 + lr];
                const uint32_t b1 = Vs[(kk + 4 + lq) * VP + nt * 8 + lr];
                mma_tf32(o[nt], a, b0, b1);
            }
        }
    }

    // write ctx directly as bf16 [B*S, H*64]
    const int b = bh >> 4;
    const int h = bh & 15;
    const float inv0 = 1.f / lsum0;
    const float inv1 = 1.f / lsum1;
    const int srow = qt * 128 + wid * 16 + lr;
#pragma unroll
    for (int nt = 0; nt < 8; nt++) {
        const int d = nt * 8 + 2 * lq;
        __nv_bfloat162 p0 = __floats2bfloat162_rn(o[nt][0] * inv0, o[nt][1] * inv0);
        __nv_bfloat162 p1 = __floats2bfloat162_rn(o[nt][2] * inv1, o[nt][3] * inv1);
        *(uint32_t*)&ctx[(size_t)(b * NS + srow) * NDM + h * 64 + d] = *(uint32_t*)&p0;
        *(uint32_t*)&ctx[(size_t)(b * NS + srow + 8) * NDM + h * 64 + d] = *(uint32_t*)&p1;
    }
}

// ---------------------------------------------------------------------------
// Fused residual + LayerNorm (in-place on out)
// ---------------------------------------------------------------------------
__global__ __launch_bounds__(256) void ln_kernel(const float* __restrict__ Qin,
                                                 const float* __restrict__ gamma,
                                                 const float* __restrict__ beta,
                                                 float* __restrict__ out) {
    __shared__ float rs[8], rq[8], fin[2];
    const int row = blockIdx.x;
    const int tid = threadIdx.x;
    const int c   = tid << 2;

    float4 o4 = *(const float4*)(out + (size_t)row * NDM + c);
    float4 q4 = *(const float4*)(Qin + (size_t)row * NDM + c);
    const float x0 = o4.x + q4.x, x1 = o4.y + q4.y, x2 = o4.z + q4.z, x3 = o4.w + q4.w;
    float s  = x0 + x1 + x2 + x3;
    float sq = x0 * x0 + x1 * x1 + x2 * x2 + x3 * x3;
#pragma unroll
    for (int off = 16; off; off >>= 1) {
        s  += __shfl_xor_sync(0xffffffffu, s, off);
        sq += __shfl_xor_sync(0xffffffffu, sq, off);
    }
    const int wid = tid >> 5, lane = tid & 31;
    if (lane == 0) { rs[wid] = s; rq[wid] = sq; }
    __syncthreads();
    if (tid == 0) {
        float a = 0.f, b2 = 0.f;
#pragma unroll
        for (int i = 0; i < 8; i++) { a += rs[i]; b2 += rq[i]; }
        fin[0] = a;
        fin[1] = b2;
    }
    __syncthreads();
    const float mu   = fin[0] * (1.0f / NDM);
    const float var  = fin[1] * (1.0f / NDM) - mu * mu;
    const float rstd = rsqrtf(var + 1e-5f);

    float4 g4 = *(const float4*)(gamma + c);
    float4 b4 = *(const float4*)(beta + c);
    float4 r;
    r.x = (x0 - mu) * rstd * g4.x + b4.x;
    r.y = (x1 - mu) * rstd * g4.y + b4.y;
    r.z = (x2 - mu) * rstd * g4.z + b4.z;
    r.w = (x3 - mu) * rstd * g4.w + b4.w;
    *(float4*)(out + (size_t)row * NDM + c) = r;
}

// ---------------------------------------------------------------------------
// Launch
// ---------------------------------------------------------------------------
extern "C" void kernel_launch(void* const* d_in, const int* in_sizes, int n_in,
                              void* d_out, int out_size) {
    const float* Q     = (const float*)d_in[0];
    const float* K     = (const float*)d_in[1];
    const float* V     = (const float*)d_in[2];
    const float* W_Q   = (const float*)d_in[3];
    const float* W_K   = (const float*)d_in[4];
    const float* W_V   = (const float*)d_in[5];
    const float* W_O   = (const float*)d_in[6];
    const float* gamma = (const float*)d_in[7];
    const float* beta  = (const float*)d_in[8];
    float* out = (float*)d_out;

    float *qh, *kh, *vh;
    __nv_bfloat16 *qb, *kb, *vb, *ctxb, *wtq, *wtk, *wtv, *wto;
    cudaGetSymbolAddress((void**)&qh,   g_Qh);
    cudaGetSymbolAddress((void**)&kh,   g_Kh);
    cudaGetSymbolAddress((void**)&vh,   g_Vh);
    cudaGetSymbolAddress((void**)&ctxb, g_ctxb);
    cudaGetSymbolAddress((void**)&qb,   g_Qb);
    cudaGetSymbolAddress((void**)&kb,   g_Kb);
    cudaGetSymbolAddress((void**)&vb,   g_Vb);
    cudaGetSymbolAddress((void**)&wtq,  g_WTq);
    cudaGetSymbolAddress((void**)&wtk,  g_WTk);
    cudaGetSymbolAddress((void**)&wtv,  g_WTv);
    cudaGetSymbolAddress((void**)&wto,  g_WTo);

    cudaFuncSetAttribute(attn_tc, cudaFuncAttributeMaxDynamicSharedMemorySize,
                         ATTN_SMEM_BYTES);

    const int convBlocks = NM * NDM / (256 * 4);   // 8192
    const dim3 tb(32, 32);

    // conversions
    f2b_kernel<<<convBlocks, 256>>>(Q, qb);
    f2b_kernel<<<convBlocks, 256>>>(K, kb);
    f2b_kernel<<<convBlocks, 256>>>(V, vb);
    wtrans_kernel<<<tb, 256>>>(W_Q, wtq);
    wtrans_kernel<<<tb, 256>>>(W_K, wtk);
    wtrans_kernel<<<tb, 256>>>(W_V, wtv);
    wtrans_kernel<<<tb, 256>>>(W_O, wto);

    // projections (bf16 mma.sync)
    const dim3 gg(NDM / 128, NM / 128);   // (8, 64)
    gemm_bf<true><<<gg, 256>>>(qb, wtq, qh);
    gemm_bf<true><<<gg, 256>>>(kb, wtk, kh);
    gemm_bf<true><<<gg, 256>>>(vb, wtv, vh);

    // attention (tf32 mma.sync), writes bf16 ctx
    attn_tc<<<dim3(NS / 128, NB * NH), 256, ATTN_SMEM_BYTES>>>(qh, kh, vh, ctxb);

    // output projection (bf16 mma.sync) + residual LN
    gemm_bf<false><<<gg, 256>>>(ctxb, wto, out);
    ln_kernel<<<NM, 256>>>(Q, gamma, beta, out);
}

// round 5
// speedup vs baseline: 4.8555x; 1.2592x over previous
#include <cuda_runtime.h>
#include <cuda_bf16.h>
#include <cstdint>

// Problem constants
#define NB   4
#define NS   2048
#define NDM  1024
#define NH   16
#define NM   (NB * NS)      // 8192 rows

// ---------------------------------------------------------------------------
// Device scratch
// ---------------------------------------------------------------------------
__device__ float g_Qh[NB * NH * NS * 64];        // tf32-rounded fp32 heads [B,H,S,64]
__device__ float g_Kh[NB * NH * NS * 64];
__device__ __nv_bfloat16 g_Vhb[NB * NH * NS * 64]; // bf16 V heads [B,H,S,64]
__device__ __nv_bfloat16 g_VT[NB * NH * 64 * NS];  // bf16 V^T [B*H,64,S]
__device__ __nv_bfloat16 g_ctxb[NM * NDM];       // bf16 ctx [B*S, H*Dv]

__device__ __nv_bfloat16 g_Qb[NM * NDM];         // bf16 activations [m][k]
__device__ __nv_bfloat16 g_Kb[NM * NDM];
__device__ __nv_bfloat16 g_Vb[NM * NDM];
__device__ __nv_bfloat16 g_WTq[NDM * NDM];       // bf16 W^T [n][k]
__device__ __nv_bfloat16 g_WTk[NDM * NDM];
__device__ __nv_bfloat16 g_WTv[NDM * NDM];
__device__ __nv_bfloat16 g_WTo[NDM * NDM];

// ---------------------------------------------------------------------------
// mma / ldmatrix helpers
// ---------------------------------------------------------------------------
__device__ __forceinline__ uint32_t f2tf(float x) {
    uint32_t r;
    asm("cvt.rna.tf32.f32 %0, %1;" : "=r"(r) : "f"(x));
    return r;
}

__device__ __forceinline__ uint32_t smem_u32(const void* p) {
    uint32_t a;
    asm("{ .reg .u64 t; cvta.to.shared.u64 t, %1; cvt.u32.u64 %0, t; }"
        : "=r"(a) : "l"(p));
    return a;
}

__device__ __forceinline__ void ldsm4(uint32_t r[4], uint32_t addr) {
    asm volatile("ldmatrix.sync.aligned.m8n8.x4.shared.b16 {%0,%1,%2,%3}, [%4];"
                 : "=r"(r[0]), "=r"(r[1]), "=r"(r[2]), "=r"(r[3]) : "r"(addr));
}

__device__ __forceinline__ void mma_tf32(float c[4], const uint32_t a[4],
                                         uint32_t b0, uint32_t b1) {
    asm volatile(
        "mma.sync.aligned.m16n8k8.row.col.f32.tf32.tf32.f32 "
        "{%0,%1,%2,%3}, {%4,%5,%6,%7}, {%8,%9}, {%0,%1,%2,%3};"
        : "+f"(c[0]), "+f"(c[1]), "+f"(c[2]), "+f"(c[3])
        : "r"(a[0]), "r"(a[1]), "r"(a[2]), "r"(a[3]), "r"(b0), "r"(b1));
}

__device__ __forceinline__ void mma_bf16(float c[4], const uint32_t a[4],
                                         uint32_t b0, uint32_t b1) {
    asm volatile(
        "mma.sync.aligned.m16n8k16.row.col.f32.bf16.bf16.f32 "
        "{%0,%1,%2,%3}, {%4,%5,%6,%7}, {%8,%9}, {%0,%1,%2,%3};"
        : "+f"(c[0]), "+f"(c[1]), "+f"(c[2]), "+f"(c[3])
        : "r"(a[0]), "r"(a[1]), "r"(a[2]), "r"(a[3]), "r"(b0), "r"(b1));
}

// ---------------------------------------------------------------------------
// Conversion kernels
// ---------------------------------------------------------------------------
__global__ __launch_bounds__(256) void f2b_kernel(const float* __restrict__ in,
                                                  __nv_bfloat16* __restrict__ out) {
    const int i = (blockIdx.x * 256 + threadIdx.x) * 4;
    float4 v = *(const float4*)(in + i);
    __nv_bfloat162 a = __floats2bfloat162_rn(v.x, v.y);
    __nv_bfloat162 b = __floats2bfloat162_rn(v.z, v.w);
    uint2 u;
    u.x = *(uint32_t*)&a;
    u.y = *(uint32_t*)&b;
    *(uint2*)(out + i) = u;
}

// W [k][n] fp32 -> WT [n][k] bf16 (tiled transpose)
__global__ __launch_bounds__(256) void wtrans_kernel(const float* __restrict__ W,
                                                     __nv_bfloat16* __restrict__ WT) {
    __shared__ float t[32][33];
    const int tx = threadIdx.x & 31;
    const int ty = threadIdx.x >> 5;
    const int bn = blockIdx.x * 32;
    const int bk = blockIdx.y * 32;
#pragma unroll
    for (int i = 0; i < 4; i++)
        t[ty + 8 * i][tx] = W[(size_t)(bk + ty + 8 * i) * NDM + bn + tx];
    __syncthreads();
#pragma unroll
    for (int i = 0; i < 4; i++)
        WT[(size_t)(bn + ty + 8 * i) * NDM + bk + tx] =
            __float2bfloat16(t[tx][ty + 8 * i]);
}

// V heads bf16 [B*H, S, 64] -> V^T bf16 [B*H, 64, S]
__global__ __launch_bounds__(256) void vtrans_kernel(const __nv_bfloat16* __restrict__ Vhb,
                                                     __nv_bfloat16* __restrict__ VT) {
    __shared__ __nv_bfloat16 t[64][72];
    const int tid = threadIdx.x;
    const int bh  = blockIdx.y;
    const int s0  = blockIdx.x * 64;
#pragma unroll
    for (int i = 0; i < 2; i++) {
        const int idx = tid + 256 * i;
        const int sr = idx >> 3, cu = idx & 7;
        *(uint4*)&t[sr][cu * 8] =
            *(const uint4*)(Vhb + ((size_t)bh * NS + s0 + sr) * 64 + cu * 8);
    }
    __syncthreads();
#pragma unroll
    for (int i = 0; i < 2; i++) {
        const int idx = tid + 256 * i;
        const int d = idx >> 3, cu = idx & 7;
        __nv_bfloat16 tmp[8];
#pragma unroll
        for (int j = 0; j < 8; j++) tmp[j] = t[cu * 8 + j][d];
        *(uint4*)&VT[((size_t)bh * 64 + d) * NS + s0 + cu * 8] = *(uint4*)tmp;
    }
}

// ---------------------------------------------------------------------------
// bf16 mma.sync GEMM (ldmatrix + 2-stage smem pipeline)
// C[8192,1024] = A_bf[m][k] @ WT_bf[n][k]^T
// BM=128, BN=128, BK=32; 8 warps, warp tile 32x64.
// MODE 0: fp32 [m][1024]; MODE 1: tf32-rounded fp32 heads [B,H,S,64];
// MODE 2: bf16 heads [B,H,S,64].
// ---------------------------------------------------------------------------
#define GW 20   // 32-bit words per smem row
#define GSTAGE (128 * GW * 4)

template <int MODE>
__global__ __launch_bounds__(256) void gemm_bf(const __nv_bfloat16* __restrict__ A,
                                               const __nv_bfloat16* __restrict__ BT,
                                               void* __restrict__ Cv) {
    __shared__ __align__(16) uint32_t As[2][128 * GW];
    __shared__ __align__(16) uint32_t Bs[2][128 * GW];

    const int tid  = threadIdx.x;
    const int lane = tid & 31;
    const int wid  = tid >> 5;
    const int lr   = lane >> 2;
    const int lq   = lane & 3;
    const int wm0  = (wid & 3) * 32;
    const int wn0  = (wid >> 2) * 64;
    const int m0   = blockIdx.y * 128;
    const int n0   = blockIdx.x * 128;

    const uint32_t AsU = smem_u32(As);
    const uint32_t BsU = smem_u32(Bs);

    // ldmatrix lane address components
    const int a_row = wm0 + (lane & 7) + (lane & 8);
    const int a_wrd = (lane >> 4) << 2;
    const int b_row = wn0 + (lane & 7) + ((lane & 16) >> 1);
    const int b_wrd = (lane & 8) ? 4 : 0;

    // gmem load mapping
    const int r0 = tid >> 2;
    const int cu = tid & 3;
    const uint8_t* Ag = (const uint8_t*)A + (size_t)m0 * 2048 + cu * 16;
    const uint8_t* Bg = (const uint8_t*)BT + (size_t)n0 * 2048 + cu * 16;

    uint4 ra[2], rb[2];
#pragma unroll
    for (int i = 0; i < 2; i++) {
        ra[i] = *(const uint4*)(Ag + (size_t)(r0 + 64 * i) * 2048);
        rb[i] = *(const uint4*)(Bg + (size_t)(r0 + 64 * i) * 2048);
    }

    float acc[2][8][4];
#pragma unroll
    for (int mi = 0; mi < 2; mi++)
#pragma unroll
        for (int nt = 0; nt < 8; nt++)
#pragma unroll
            for (int v = 0; v < 4; v++) acc[mi][nt][v] = 0.f;

    // prologue: stage 0
#pragma unroll
    for (int i = 0; i < 2; i++) {
        const int off = (r0 + 64 * i) * GW + cu * 4;
        *(uint4*)&As[0][off] = ra[i];
        *(uint4*)&Bs[0][off] = rb[i];
    }
    __syncthreads();

    for (int c = 0; c < 32; c++) {
        const int st = c & 1;
        if (c < 31) {
            const size_t koff = (size_t)(c + 1) * 64;
#pragma unroll
            for (int i = 0; i < 2; i++) {
                ra[i] = *(const uint4*)(Ag + (size_t)(r0 + 64 * i) * 2048 + koff);
                rb[i] = *(const uint4*)(Bg + (size_t)(r0 + 64 * i) * 2048 + koff);
            }
        }

#pragma unroll
        for (int s = 0; s < 2; s++) {
            uint32_t a[2][4];
            ldsm4(a[0], AsU + st * GSTAGE + ((a_row)*GW + s * 8 + a_wrd) * 4);
            ldsm4(a[1], AsU + st * GSTAGE + ((a_row + 16) * GW + s * 8 + a_wrd) * 4);
#pragma unroll
            for (int np = 0; np < 4; np++) {
                uint32_t bb[4];
                ldsm4(bb, BsU + st * GSTAGE + ((b_row + np * 16) * GW + s * 8 + b_wrd) * 4);
                mma_bf16(acc[0][2 * np],     a[0], bb[0], bb[1]);
                mma_bf16(acc[1][2 * np],     a[1], bb[0], bb[1]);
                mma_bf16(acc[0][2 * np + 1], a[0], bb[2], bb[3]);
                mma_bf16(acc[1][2 * np + 1], a[1], bb[2], bb[3]);
            }
        }

        if (c < 31) {
            const int st2 = st ^ 1;
#pragma unroll
            for (int i = 0; i < 2; i++) {
                const int off = (r0 + 64 * i) * GW + cu * 4;
                *(uint4*)&As[st2][off] = ra[i];
                *(uint4*)&Bs[st2][off] = rb[i];
            }
            __syncthreads();
        }
    }

    // Epilogue
#pragma unroll
    for (int mi = 0; mi < 2; mi++) {
        const int row0 = m0 + wm0 + mi * 16 + lr;
#pragma unroll
        for (int nt = 0; nt < 8; nt++) {
            const int col = wn0 + nt * 8 + 2 * lq;   // 0..127 within block
            if (MODE == 1) {
                float* C = (float*)Cv;
                float2 v0, v1;
                v0.x = __uint_as_float(f2tf(acc[mi][nt][0]));
                v0.y = __uint_as_float(f2tf(acc[mi][nt][1]));
                v1.x = __uint_as_float(f2tf(acc[mi][nt][2]));
                v1.y = __uint_as_float(f2tf(acc[mi][nt][3]));
                const int gcol = n0 + col;
                const int h = gcol >> 6, d = gcol & 63;
                const int b0i = row0 >> 11, s0 = row0 & 2047;
                *(float2*)&C[(size_t)((b0i * NH + h) * NS + s0) * 64 + d] = v0;
                const int row1 = row0 + 8;
                const int b1i = row1 >> 11, s1 = row1 & 2047;
                *(float2*)&C[(size_t)((b1i * NH + h) * NS + s1) * 64 + d] = v1;
            } else if (MODE == 2) {
                __nv_bfloat16* C = (__nv_bfloat16*)Cv;
                __nv_bfloat162 v0 = __floats2bfloat162_rn(acc[mi][nt][0], acc[mi][nt][1]);
                __nv_bfloat162 v1 = __floats2bfloat162_rn(acc[mi][nt][2], acc[mi][nt][3]);
                const int gcol = n0 + col;
                const int h = gcol >> 6, d = gcol & 63;
                const int b0i = row0 >> 11, s0 = row0 & 2047;
                *(uint32_t*)&C[(size_t)((b0i * NH + h) * NS + s0) * 64 + d] = *(uint32_t*)&v0;
                const int row1 = row0 + 8;
                const int b1i = row1 >> 11, s1 = row1 & 2047;
                *(uint32_t*)&C[(size_t)((b1i * NH + h) * NS + s1) * 64 + d] = *(uint32_t*)&v1;
            } else {
                float* C = (float*)Cv;
                *(float2*)&C[(size_t)row0 * NDM + n0 + col] =
                    make_float2(acc[mi][nt][0], acc[mi][nt][1]);
                *(float2*)&C[(size_t)(row0 + 8) * NDM + n0 + col] =
                    make_float2(acc[mi][nt][2], acc[mi][nt][3]);
            }
        }
    }
}

// ---------------------------------------------------------------------------
// Flash attention, causal. QK^T in tf32 mma, PV in bf16 mma.
// Q tile 128, K tile 64. 8 warps; warp w owns q-rows [16w,16w+16).
// Q/K heads are tf32-pre-rounded fp32; V supplied transposed bf16 [64][S].
// ---------------------------------------------------------------------------
#define AP 68
#define PW 36
#define VW 36
#define ATTN_SMEM_BYTES ((128 * AP + 64 * AP + 128 * PW + 64 * VW) * 4)

__global__ __launch_bounds__(256) void attn_tc(const float* __restrict__ Qh,
                                               const float* __restrict__ Kh,
                                               const __nv_bfloat16* __restrict__ VT,
                                               __nv_bfloat16* __restrict__ ctx) {
    extern __shared__ uint32_t sm[];
    uint32_t* Qs = sm;                    // [128][68] tf32
    uint32_t* Ks = Qs + 128 * AP;         // [64][68]  tf32
    uint32_t* Ps = Ks + 64 * AP;          // [128][36] bf16 pairs
    uint32_t* Vt = Ps + 128 * PW;         // [64][36]  bf16 pairs (V^T: row d, k pairs)

    const int tid  = threadIdx.x;
    const int lane = tid & 31;
    const int wid  = tid >> 5;
    const int lr   = lane >> 2;
    const int lq   = lane & 3;

    const int qt = gridDim.x - 1 - blockIdx.x;   // heavy tiles first
    const int bh = blockIdx.y;

    const float* Qb = Qh + (size_t)bh * NS * 64;
    const float* Kb = Kh + (size_t)bh * NS * 64;

    {
        const int r0 = tid >> 4;
        const int c  = (tid & 15) << 2;
#pragma unroll
        for (int i = 0; i < 8; i++) {
            const int r = r0 + 16 * i;
            uint4 q = *(const uint4*)(Qb + (size_t)(qt * 128 + r) * 64 + c);
            Qs[r * AP + c + 0] = q.x;
            Qs[r * AP + c + 1] = q.y;
            Qs[r * AP + c + 2] = q.z;
            Qs[r * AP + c + 3] = q.w;
        }
    }

    float o[8][4];
#pragma unroll
    for (int nt = 0; nt < 8; nt++)
#pragma unroll
        for (int v = 0; v < 4; v++) o[nt][v] = 0.f;
    float mrow0 = -1e30f, mrow1 = -1e30f, lsum0 = 0.f, lsum1 = 0.f;

    const int qrow0 = qt * 128 + wid * 16 + lr;
    const int qrow1 = qrow0 + 8;
    const int ktmax = 2 * qt + 1;

    for (int kt = 0; kt <= ktmax; kt++) {
        __syncthreads();
        {   // K tile: fp32 bit copy [64][64]
            const int r0 = tid >> 4;
            const int c  = (tid & 15) << 2;
#pragma unroll
            for (int i = 0; i < 4; i++) {
                const int r = r0 + 16 * i;
                uint4 kv = *(const uint4*)(Kb + (size_t)(kt * 64 + r) * 64 + c);
                Ks[r * AP + c + 0] = kv.x;
                Ks[r * AP + c + 1] = kv.y;
                Ks[r * AP + c + 2] = kv.z;
                Ks[r * AP + c + 3] = kv.w;
            }
            // V^T tile: bf16 [64 d][64 k] rows, coalesced
#pragma unroll
            for (int i = 0; i < 2; i++) {
                const int idx = tid + 256 * i;
                const int d = idx >> 3, cv = idx & 7;
                uint4 vv = *(const uint4*)(VT + ((size_t)bh * 64 + d) * NS + kt * 64 + cv * 8);
                *(uint4*)&Vt[d * VW + cv * 4] = vv;
            }
        }
        __syncthreads();

        // ---- S = Q K^T (tf32) ----
        float s[8][4];
#pragma unroll
        for (int nt = 0; nt < 8; nt++)
#pragma unroll
            for (int v = 0; v < 4; v++) s[nt][v] = 0.f;

#pragma unroll
        for (int kk = 0; kk < 64; kk += 8) {
            uint32_t a[4];
            const uint32_t* qb = &Qs[(wid * 16 + lr) * AP + kk + lq];
            a[0] = qb[0];
            a[1] = qb[8 * AP];
            a[2] = qb[4];
            a[3] = qb[8 * AP + 4];
#pragma unroll
            for (int nt = 0; nt < 8; nt++) {
                const uint32_t b0 = Ks[(nt * 8 + lr) * AP + kk + lq];
                const uint32_t b1 = Ks[(nt * 8 + lr) * AP + kk + 4 + lq];
                mma_tf32(s[nt], a, b0, b1);
            }
        }

        const bool diag = (kt >= 2 * qt);
#pragma unroll
        for (int nt = 0; nt < 8; nt++) {
            const int col = kt * 64 + nt * 8 + 2 * lq;
            s[nt][0] *= 0.125f;
            s[nt][1] *= 0.125f;
            s[nt][2] *= 0.125f;
            s[nt][3] *= 0.125f;
            if (diag) {
                if (col     > qrow0) s[nt][0] = -1e30f;
                if (col + 1 > qrow0) s[nt][1] = -1e30f;
                if (col     > qrow1) s[nt][2] = -1e30f;
                if (col + 1 > qrow1) s[nt][3] = -1e30f;
            }
        }

        // ---- online softmax ----
        float mx0 = -1e30f, mx1 = -1e30f;
#pragma unroll
        for (int nt = 0; nt < 8; nt++) {
            mx0 = fmaxf(mx0, fmaxf(s[nt][0], s[nt][1]));
            mx1 = fmaxf(mx1, fmaxf(s[nt][2], s[nt][3]));
        }
        mx0 = fmaxf(mx0, __shfl_xor_sync(0xffffffffu, mx0, 1));
        mx0 = fmaxf(mx0, __shfl_xor_sync(0xffffffffu, mx0, 2));
        mx1 = fmaxf(mx1, __shfl_xor_sync(0xffffffffu, mx1, 1));
        mx1 = fmaxf(mx1, __shfl_xor_sync(0xffffffffu, mx1, 2));

        const float mn0 = fmaxf(mrow0, mx0);
        const float mn1 = fmaxf(mrow1, mx1);
        const float corr0 = __expf(mrow0 - mn0);
        const float corr1 = __expf(mrow1 - mn1);

        float rs0 = 0.f, rs1 = 0.f;
#pragma unroll
        for (int nt = 0; nt < 8; nt++) {
            s[nt][0] = __expf(s[nt][0] - mn0);
            s[nt][1] = __expf(s[nt][1] - mn0);
            s[nt][2] = __expf(s[nt][2] - mn1);
            s[nt][3] = __expf(s[nt][3] - mn1);
            rs0 += s[nt][0] + s[nt][1];
            rs1 += s[nt][2] + s[nt][3];
        }
        rs0 += __shfl_xor_sync(0xffffffffu, rs0, 1);
        rs0 += __shfl_xor_sync(0xffffffffu, rs0, 2);
        rs1 += __shfl_xor_sync(0xffffffffu, rs1, 1);
        rs1 += __shfl_xor_sync(0xffffffffu, rs1, 2);

        lsum0 = lsum0 * corr0 + rs0;
        lsum1 = lsum1 * corr1 + rs1;
        mrow0 = mn0;
        mrow1 = mn1;
#pragma unroll
        for (int nt = 0; nt < 8; nt++) {
            o[nt][0] *= corr0;
            o[nt][1] *= corr0;
            o[nt][2] *= corr1;
            o[nt][3] *= corr1;
        }

        // ---- store P as bf16 pairs (warp-private rows) ----
#pragma unroll
        for (int nt = 0; nt < 8; nt++) {
            __nv_bfloat162 p0 = __floats2bfloat162_rn(s[nt][0], s[nt][1]);
            __nv_bfloat162 p1 = __floats2bfloat162_rn(s[nt][2], s[nt][3]);
            Ps[(wid * 16 + lr) * PW + nt * 4 + lq]     = *(uint32_t*)&p0;
            Ps[(wid * 16 + lr + 8) * PW + nt * 4 + lq] = *(uint32_t*)&p1;
        }
        __syncwarp();

        // ---- O += P V (bf16, 4 k16 steps) ----
#pragma unroll
        for (int step = 0; step < 4; step++) {
            uint32_t a[4];
            const uint32_t* pb = &Ps[(wid * 16 + lr) * PW + step * 8 + lq];
            a[0] = pb[0];
            a[1] = pb[8 * PW];
            a[2] = pb[4];
            a[3] = pb[8 * PW + 4];
#pragma unroll
            for (int nt = 0; nt < 8; nt++) {
                const uint32_t b0 = Vt[(nt * 8 + lr) * VW + step * 8 + lq];
                const uint32_t b1 = Vt[(nt * 8 + lr) * VW + step * 8 + 4 + lq];
                mma_bf16(o[nt], a, b0, b1);
            }
        }
    }

    // write ctx directly as bf16 [B*S, H*64]
    const int b = bh >> 4;
    const int h = bh & 15;
    const float inv0 = 1.f / lsum0;
    const float inv1 = 1.f / lsum1;
    const int srow = qt * 128 + wid * 16 + lr;
#pragma unroll
    for (int nt = 0; nt < 8; nt++) {
        const int d = nt * 8 + 2 * lq;
        __nv_bfloat162 p0 = __floats2bfloat162_rn(o[nt][0] * inv0, o[nt][1] * inv0);
        __nv_bfloat162 p1 = __floats2bfloat162_rn(o[nt][2] * inv1, o[nt][3] * inv1);
        *(uint32_t*)&ctx[(size_t)(b * NS + srow) * NDM + h * 64 + d] = *(uint32_t*)&p0;
        *(uint32_t*)&ctx[(size_t)(b * NS + srow + 8) * NDM + h * 64 + d] = *(uint32_t*)&p1;
    }
}

// ---------------------------------------------------------------------------
// Fused residual + LayerNorm (in-place on out)
// ---------------------------------------------------------------------------
__global__ __launch_bounds__(256) void ln_kernel(const float* __restrict__ Qin,
                                                 const float* __restrict__ gamma,
                                                 const float* __restrict__ beta,
                                                 float* __restrict__ out) {
    __shared__ float rs[8], rq[8], fin[2];
    const int row = blockIdx.x;
    const int tid = threadIdx.x;
    const int c   = tid << 2;

    float4 o4 = *(const float4*)(out + (size_t)row * NDM + c);
    float4 q4 = *(const float4*)(Qin + (size_t)row * NDM + c);
    const float x0 = o4.x + q4.x, x1 = o4.y + q4.y, x2 = o4.z + q4.z, x3 = o4.w + q4.w;
    float s  = x0 + x1 + x2 + x3;
    float sq = x0 * x0 + x1 * x1 + x2 * x2 + x3 * x3;
#pragma unroll
    for (int off = 16; off; off >>= 1) {
        s  += __shfl_xor_sync(0xffffffffu, s, off);
        sq += __shfl_xor_sync(0xffffffffu, sq, off);
    }
    const int wid = tid >> 5, lane = tid & 31;
    if (lane == 0) { rs[wid] = s; rq[wid] = sq; }
    __syncthreads();
    if (tid == 0) {
        float a = 0.f, b2 = 0.f;
#pragma unroll
        for (int i = 0; i < 8; i++) { a += rs[i]; b2 += rq[i]; }
        fin[0] = a;
        fin[1] = b2;
    }
    __syncthreads();
    const float mu   = fin[0] * (1.0f / NDM);
    const float var  = fin[1] * (1.0f / NDM) - mu * mu;
    const float rstd = rsqrtf(var + 1e-5f);

    float4 g4 = *(const float4*)(gamma + c);
    float4 b4 = *(const float4*)(beta + c);
    float4 r;
    r.x = (x0 - mu) * rstd * g4.x + b4.x;
    r.y = (x1 - mu) * rstd * g4.y + b4.y;
    r.z = (x2 - mu) * rstd * g4.z + b4.z;
    r.w = (x3 - mu) * rstd * g4.w + b4.w;
    *(float4*)(out + (size_t)row * NDM + c) = r;
}

// ---------------------------------------------------------------------------
// Launch
// ---------------------------------------------------------------------------
extern "C" void kernel_launch(void* const* d_in, const int* in_sizes, int n_in,
                              void* d_out, int out_size) {
    const float* Q     = (const float*)d_in[0];
    const float* K     = (const float*)d_in[1];
    const float* V     = (const float*)d_in[2];
    const float* W_Q   = (const float*)d_in[3];
    const float* W_K   = (const float*)d_in[4];
    const float* W_V   = (const float*)d_in[5];
    const float* W_O   = (const float*)d_in[6];
    const float* gamma = (const float*)d_in[7];
    const float* beta  = (const float*)d_in[8];
    float* out = (float*)d_out;

    float *qh, *kh;
    __nv_bfloat16 *vhb, *vt, *qb, *kb, *vb, *ctxb, *wtq, *wtk, *wtv, *wto;
    cudaGetSymbolAddress((void**)&qh,   g_Qh);
    cudaGetSymbolAddress((void**)&kh,   g_Kh);
    cudaGetSymbolAddress((void**)&vhb,  g_Vhb);
    cudaGetSymbolAddress((void**)&vt,   g_VT);
    cudaGetSymbolAddress((void**)&ctxb, g_ctxb);
    cudaGetSymbolAddress((void**)&qb,   g_Qb);
    cudaGetSymbolAddress((void**)&kb,   g_Kb);
    cudaGetSymbolAddress((void**)&vb,   g_Vb);
    cudaGetSymbolAddress((void**)&wtq,  g_WTq);
    cudaGetSymbolAddress((void**)&wtk,  g_WTk);
    cudaGetSymbolAddress((void**)&wtv,  g_WTv);
    cudaGetSymbolAddress((void**)&wto,  g_WTo);

    cudaFuncSetAttribute(attn_tc, cudaFuncAttributeMaxDynamicSharedMemorySize,
                         ATTN_SMEM_BYTES);

    const int convBlocks = NM * NDM / (256 * 4);   // 8192
    const dim3 tb(32, 32);

    // conversions
    f2b_kernel<<<convBlocks, 256>>>(Q, qb);
    f2b_kernel<<<convBlocks, 256>>>(K, kb);
    f2b_kernel<<<convBlocks, 256>>>(V, vb);
    wtrans_kernel<<<tb, 256>>>(W_Q, wtq);
    wtrans_kernel<<<tb, 256>>>(W_K, wtk);
    wtrans_kernel<<<tb, 256>>>(W_V, wtv);
    wtrans_kernel<<<tb, 256>>>(W_O, wto);

    // projections
    const dim3 gg(NDM / 128, NM / 128);   // (8, 64)
    gemm_bf<1><<<gg, 256>>>(qb, wtq, qh);
    gemm_bf<1><<<gg, 256>>>(kb, wtk, kh);
    gemm_bf<2><<<gg, 256>>>(vb, wtv, vhb);
    vtrans_kernel<<<dim3(NS / 64, NB * NH), 256>>>(vhb, vt);

    // attention (tf32 QK^T, bf16 PV), writes bf16 ctx
    attn_tc<<<dim3(NS / 128, NB * NH), 256, ATTN_SMEM_BYTES>>>(qh, kh, vt, ctxb);

    // output projection + residual LN
    gemm_bf<0><<<gg, 256>>>(ctxb, wto, out);
    ln_kernel<<<NM, 256>>>(Q, gamma, beta, out);
}

// round 6
// speedup vs baseline: 5.8676x; 1.2084x over previous
#include <cuda_runtime.h>
#include <cuda_fp16.h>
#include <cstdint>

// Problem constants
#define NB   4
#define NS   2048
#define NDM  1024
#define NH   16
#define NM   (NB * NS)      // 8192 rows

// ---------------------------------------------------------------------------
// Device scratch
// ---------------------------------------------------------------------------
__device__ __half g_Qh[NB * NH * NS * 64];   // fp16 heads [B,H,S,64]
__device__ __half g_Kh[NB * NH * NS * 64];
__device__ __half g_Vh[NB * NH * NS * 64];
__device__ __half g_ctxh[NM * NDM];          // fp16 ctx [B*S, H*Dv]

__device__ __half g_Qb[NM * NDM];            // fp16 activations [m][k]
__device__ __half g_Kb[NM * NDM];
__device__ __half g_Vb[NM * NDM];
__device__ __half g_WTq[NDM * NDM];          // fp16 W^T [n][k]
__device__ __half g_WTk[NDM * NDM];
__device__ __half g_WTv[NDM * NDM];
__device__ __half g_WTo[NDM * NDM];

// ---------------------------------------------------------------------------
// mma / ldmatrix helpers
// ---------------------------------------------------------------------------
__device__ __forceinline__ uint32_t smem_u32(const void* p) {
    uint32_t a;
    asm("{ .reg .u64 t; cvta.to.shared.u64 t, %1; cvt.u32.u64 %0, t; }"
        : "=r"(a) : "l"(p));
    return a;
}

__device__ __forceinline__ void ldsm4(uint32_t r[4], uint32_t addr) {
    asm volatile("ldmatrix.sync.aligned.m8n8.x4.shared.b16 {%0,%1,%2,%3}, [%4];"
                 : "=r"(r[0]), "=r"(r[1]), "=r"(r[2]), "=r"(r[3]) : "r"(addr));
}

__device__ __forceinline__ void ldsm4t(uint32_t r[4], uint32_t addr) {
    asm volatile("ldmatrix.sync.aligned.m8n8.x4.trans.shared.b16 {%0,%1,%2,%3}, [%4];"
                 : "=r"(r[0]), "=r"(r[1]), "=r"(r[2]), "=r"(r[3]) : "r"(addr));
}

__device__ __forceinline__ void mma_f16(float c[4], const uint32_t a[4],
                                        uint32_t b0, uint32_t b1) {
    asm volatile(
        "mma.sync.aligned.m16n8k16.row.col.f32.f16.f16.f32 "
        "{%0,%1,%2,%3}, {%4,%5,%6,%7}, {%8,%9}, {%0,%1,%2,%3};"
        : "+f"(c[0]), "+f"(c[1]), "+f"(c[2]), "+f"(c[3])
        : "r"(a[0]), "r"(a[1]), "r"(a[2]), "r"(a[3]), "r"(b0), "r"(b1));
}

// ---------------------------------------------------------------------------
// Conversion kernels
// ---------------------------------------------------------------------------
__global__ __launch_bounds__(256) void f2h_kernel(const float* __restrict__ in,
                                                  __half* __restrict__ out) {
    const int i = (blockIdx.x * 256 + threadIdx.x) * 4;
    float4 v = *(const float4*)(in + i);
    __half2 a = __float22half2_rn(make_float2(v.x, v.y));
    __half2 b = __float22half2_rn(make_float2(v.z, v.w));
    uint2 u;
    u.x = *(uint32_t*)&a;
    u.y = *(uint32_t*)&b;
    *(uint2*)(out + i) = u;
}

// W [k][n] fp32 -> WT [n][k] fp16 (tiled transpose)
__global__ __launch_bounds__(256) void wtrans_kernel(const float* __restrict__ W,
                                                     __half* __restrict__ WT) {
    __shared__ float t[32][33];
    const int tx = threadIdx.x & 31;
    const int ty = threadIdx.x >> 5;
    const int bn = blockIdx.x * 32;
    const int bk = blockIdx.y * 32;
#pragma unroll
    for (int i = 0; i < 4; i++)
        t[ty + 8 * i][tx] = W[(size_t)(bk + ty + 8 * i) * NDM + bn + tx];
    __syncthreads();
#pragma unroll
    for (int i = 0; i < 4; i++)
        WT[(size_t)(bn + ty + 8 * i) * NDM + bk + tx] =
            __float2half(t[tx][ty + 8 * i]);
}

// ---------------------------------------------------------------------------
// fp16 mma.sync GEMM (ldmatrix + 2-stage smem pipeline)
// C[8192,1024] = A_h[m][k] @ WT_h[n][k]^T
// BM=128, BN=128, BK=32; 8 warps, warp tile 32x64.
// MODE 0: fp32 [m][1024]; MODE 2: fp16 heads [B,H,S,64].
// ---------------------------------------------------------------------------
#define GW 20   // 32-bit words per smem row
#define GSTAGE (128 * GW * 4)

template <int MODE>
__global__ __launch_bounds__(256) void gemm_h(const __half* __restrict__ A,
                                              const __half* __restrict__ BT,
                                              void* __restrict__ Cv) {
    __shared__ __align__(16) uint32_t As[2][128 * GW];
    __shared__ __align__(16) uint32_t Bs[2][128 * GW];

    const int tid  = threadIdx.x;
    const int lane = tid & 31;
    const int wid  = tid >> 5;
    const int lr   = lane >> 2;
    const int lq   = lane & 3;
    const int wm0  = (wid & 3) * 32;
    const int wn0  = (wid >> 2) * 64;
    const int m0   = blockIdx.y * 128;
    const int n0   = blockIdx.x * 128;

    const uint32_t AsU = smem_u32(As);
    const uint32_t BsU = smem_u32(Bs);

    // ldmatrix lane address components
    const int a_row = wm0 + (lane & 7) + (lane & 8);
    const int a_wrd = (lane >> 4) << 2;
    const int b_row = wn0 + (lane & 7) + ((lane & 16) >> 1);
    const int b_wrd = (lane & 8) ? 4 : 0;

    // gmem load mapping
    const int r0 = tid >> 2;
    const int cu = tid & 3;
    const uint8_t* Ag = (const uint8_t*)A + (size_t)m0 * 2048 + cu * 16;
    const uint8_t* Bg = (const uint8_t*)BT + (size_t)n0 * 2048 + cu * 16;

    uint4 ra[2], rb[2];
#pragma unroll
    for (int i = 0; i < 2; i++) {
        ra[i] = *(const uint4*)(Ag + (size_t)(r0 + 64 * i) * 2048);
        rb[i] = *(const uint4*)(Bg + (size_t)(r0 + 64 * i) * 2048);
    }

    float acc[2][8][4];
#pragma unroll
    for (int mi = 0; mi < 2; mi++)
#pragma unroll
        for (int nt = 0; nt < 8; nt++)
#pragma unroll
            for (int v = 0; v < 4; v++) acc[mi][nt][v] = 0.f;

    // prologue: stage 0
#pragma unroll
    for (int i = 0; i < 2; i++) {
        const int off = (r0 + 64 * i) * GW + cu * 4;
        *(uint4*)&As[0][off] = ra[i];
        *(uint4*)&Bs[0][off] = rb[i];
    }
    __syncthreads();

    for (int c = 0; c < 32; c++) {
        const int st = c & 1;
        if (c < 31) {
            const size_t koff = (size_t)(c + 1) * 64;
#pragma unroll
            for (int i = 0; i < 2; i++) {
                ra[i] = *(const uint4*)(Ag + (size_t)(r0 + 64 * i) * 2048 + koff);
                rb[i] = *(const uint4*)(Bg + (size_t)(r0 + 64 * i) * 2048 + koff);
            }
        }

#pragma unroll
        for (int s = 0; s < 2; s++) {
            uint32_t a[2][4];
            ldsm4(a[0], AsU + st * GSTAGE + ((a_row)*GW + s * 8 + a_wrd) * 4);
            ldsm4(a[1], AsU + st * GSTAGE + ((a_row + 16) * GW + s * 8 + a_wrd) * 4);
#pragma unroll
            for (int np = 0; np < 4; np++) {
                uint32_t bb[4];
                ldsm4(bb, BsU + st * GSTAGE + ((b_row + np * 16) * GW + s * 8 + b_wrd) * 4);
                mma_f16(acc[0][2 * np],     a[0], bb[0], bb[1]);
                mma_f16(acc[1][2 * np],     a[1], bb[0], bb[1]);
                mma_f16(acc[0][2 * np + 1], a[0], bb[2], bb[3]);
                mma_f16(acc[1][2 * np + 1], a[1], bb[2], bb[3]);
            }
        }

        if (c < 31) {
            const int st2 = st ^ 1;
#pragma unroll
            for (int i = 0; i < 2; i++) {
                const int off = (r0 + 64 * i) * GW + cu * 4;
                *(uint4*)&As[st2][off] = ra[i];
                *(uint4*)&Bs[st2][off] = rb[i];
            }
            __syncthreads();
        }
    }

    // Epilogue
#pragma unroll
    for (int mi = 0; mi < 2; mi++) {
        const int row0 = m0 + wm0 + mi * 16 + lr;
#pragma unroll
        for (int nt = 0; nt < 8; nt++) {
            const int col = wn0 + nt * 8 + 2 * lq;   // 0..127 within block
            if (MODE == 2) {
                __half* C = (__half*)Cv;
                __half2 v0 = __float22half2_rn(make_float2(acc[mi][nt][0], acc[mi][nt][1]));
                __half2 v1 = __float22half2_rn(make_float2(acc[mi][nt][2], acc[mi][nt][3]));
                const int gcol = n0 + col;
                const int h = gcol >> 6, d = gcol & 63;
                const int b0i = row0 >> 11, s0 = row0 & 2047;
                *(uint32_t*)&C[(size_t)((b0i * NH + h) * NS + s0) * 64 + d] = *(uint32_t*)&v0;
                const int row1 = row0 + 8;
                const int b1i = row1 >> 11, s1 = row1 & 2047;
                *(uint32_t*)&C[(size_t)((b1i * NH + h) * NS + s1) * 64 + d] = *(uint32_t*)&v1;
            } else {
                float* C = (float*)Cv;
                *(float2*)&C[(size_t)row0 * NDM + n0 + col] =
                    make_float2(acc[mi][nt][0], acc[mi][nt][1]);
                *(float2*)&C[(size_t)(row0 + 8) * NDM + n0 + col] =
                    make_float2(acc[mi][nt][2], acc[mi][nt][3]);
            }
        }
    }
}

// ---------------------------------------------------------------------------
// Flash attention, causal, fully fp16 mma m16n8k16 with ldmatrix fragments.
// Q tile 128, K tile 64. 8 warps; warp w owns q-rows [16w,16w+16).
// Q fragments hoisted to registers (constant over kt loop).
// V consumed in natural [kv][d] layout via ldmatrix.trans.
// ---------------------------------------------------------------------------
#define ST 72   // halves per smem row
#define ATTN_SMEM_BYTES ((128 + 64 + 128 + 64) * ST * 2)   // 55296

__global__ __launch_bounds__(256) void attn_h(const __half* __restrict__ Qh,
                                              const __half* __restrict__ Kh,
                                              const __half* __restrict__ Vh,
                                              __half* __restrict__ ctx) {
    extern __shared__ __half smh[];
    __half* Qs = smh;              // [128][ST]
    __half* Ks = Qs + 128 * ST;    // [64][ST]
    __half* Ps = Ks + 64 * ST;     // [128][ST]
    __half* Vs = Ps + 128 * ST;    // [64][ST]
    const uint32_t qsU = smem_u32(Qs);
    const uint32_t ksU = smem_u32(Ks);
    const uint32_t psU = smem_u32(Ps);
    const uint32_t vsU = smem_u32(Vs);

    const int tid  = threadIdx.x;
    const int lane = tid & 31;
    const int wid  = tid >> 5;
    const int lr   = lane >> 2;
    const int lq   = lane & 3;

    const int qt = gridDim.x - 1 - blockIdx.x;   // heavy tiles first
    const int bh = blockIdx.y;

    const __half* Qb = Qh + (size_t)bh * NS * 64;
    const __half* Kb = Kh + (size_t)bh * NS * 64;
    const __half* Vb = Vh + (size_t)bh * NS * 64;

    // Load Q tile (128 x 64 fp16) coalesced
#pragma unroll
    for (int i = 0; i < 4; i++) {
        const int idx = tid + 256 * i;
        const int r = idx >> 3, cu = idx & 7;
        *(uint4*)&Qs[r * ST + cu * 8] =
            *(const uint4*)(Qb + (size_t)(qt * 128 + r) * 64 + cu * 8);
    }
    __syncthreads();

    // Hoist Q fragments to registers (A operand, 4 k16 steps)
    uint32_t qf[4][4];
    {
        const int arow = wid * 16 + (lane & 7) + (lane & 8);
        const int acol = (lane & 16) >> 1;
#pragma unroll
        for (int s = 0; s < 4; s++)
            ldsm4(qf[s], qsU + (uint32_t)(arow * ST + s * 16 + acol) * 2);
    }

    float o[8][4];
#pragma unroll
    for (int nt = 0; nt < 8; nt++)
#pragma unroll
        for (int v = 0; v < 4; v++) o[nt][v] = 0.f;
    float mrow0 = -1e30f, mrow1 = -1e30f, lsum0 = 0.f, lsum1 = 0.f;

    const int qrow0 = qt * 128 + wid * 16 + lr;
    const int qrow1 = qrow0 + 8;
    const int ktmax = 2 * qt + 1;

    // ldmatrix lane components
    const int kb_row = (lane & 7) + ((lane & 16) >> 1);   // K: B-operand rows (n)
    const int kb_col = (lane & 8) ? 8 : 0;                // K: k offset
    const int vb_row = (lane & 7) + (lane & 8);           // V: stored kv rows
    const int vb_col = (lane & 16) >> 1;                  // V: d offset
    const int p_row  = wid * 16 + (lane & 7) + (lane & 8);
    const int p_col  = (lane & 16) >> 1;

    for (int kt = 0; kt <= ktmax; kt++) {
        __syncthreads();   // prior iteration's Ks/Vs reads complete
#pragma unroll
        for (int i = 0; i < 2; i++) {
            const int idx = tid + 256 * i;
            const int r = idx >> 3, cu = idx & 7;
            *(uint4*)&Ks[r * ST + cu * 8] =
                *(const uint4*)(Kb + (size_t)(kt * 64 + r) * 64 + cu * 8);
            *(uint4*)&Vs[r * ST + cu * 8] =
                *(const uint4*)(Vb + (size_t)(kt * 64 + r) * 64 + cu * 8);
        }
        __syncthreads();

        // ---- S = Q K^T (fp16, 4 k16 steps) ----
        float s[8][4];
#pragma unroll
        for (int nt = 0; nt < 8; nt++)
#pragma unroll
            for (int v = 0; v < 4; v++) s[nt][v] = 0.f;

#pragma unroll
        for (int step = 0; step < 4; step++) {
#pragma unroll
            for (int np = 0; np < 4; np++) {
                uint32_t bb[4];
                ldsm4(bb, ksU + (uint32_t)((np * 16 + kb_row) * ST + step * 16 + kb_col) * 2);
                mma_f16(s[2 * np],     qf[step], bb[0], bb[1]);
                mma_f16(s[2 * np + 1], qf[step], bb[2], bb[3]);
            }
        }

        // scale + causal mask
        const bool diag = (kt >= 2 * qt);
#pragma unroll
        for (int nt = 0; nt < 8; nt++) {
            const int col = kt * 64 + nt * 8 + 2 * lq;
            s[nt][0] *= 0.125f;
            s[nt][1] *= 0.125f;
            s[nt][2] *= 0.125f;
            s[nt][3] *= 0.125f;
            if (diag) {
                if (col     > qrow0) s[nt][0] = -1e30f;
                if (col + 1 > qrow0) s[nt][1] = -1e30f;
                if (col     > qrow1) s[nt][2] = -1e30f;
                if (col + 1 > qrow1) s[nt][3] = -1e30f;
            }
        }

        // ---- online softmax (rows lr and lr+8; reduce over quad lanes) ----
        float mx0 = -1e30f, mx1 = -1e30f;
#pragma unroll
        for (int nt = 0; nt < 8; nt++) {
            mx0 = fmaxf(mx0, fmaxf(s[nt][0], s[nt][1]));
            mx1 = fmaxf(mx1, fmaxf(s[nt][2], s[nt][3]));
        }
        mx0 = fmaxf(mx0, __shfl_xor_sync(0xffffffffu, mx0, 1));
        mx0 = fmaxf(mx0, __shfl_xor_sync(0xffffffffu, mx0, 2));
        mx1 = fmaxf(mx1, __shfl_xor_sync(0xffffffffu, mx1, 1));
        mx1 = fmaxf(mx1, __shfl_xor_sync(0xffffffffu, mx1, 2));

        const float mn0 = fmaxf(mrow0, mx0);
        const float mn1 = fmaxf(mrow1, mx1);
        const float corr0 = __expf(mrow0 - mn0);
        const float corr1 = __expf(mrow1 - mn1);

        float rs0 = 0.f, rs1 = 0.f;
#pragma unroll
        for (int nt = 0; nt < 8; nt++) {
            s[nt][0] = __expf(s[nt][0] - mn0);
            s[nt][1] = __expf(s[nt][1] - mn0);
            s[nt][2] = __expf(s[nt][2] - mn1);
            s[nt][3] = __expf(s[nt][3] - mn1);
            rs0 += s[nt][0] + s[nt][1];
            rs1 += s[nt][2] + s[nt][3];
        }
        rs0 += __shfl_xor_sync(0xffffffffu, rs0, 1);
        rs0 += __shfl_xor_sync(0xffffffffu, rs0, 2);
        rs1 += __shfl_xor_sync(0xffffffffu, rs1, 1);
        rs1 += __shfl_xor_sync(0xffffffffu, rs1, 2);

        lsum0 = lsum0 * corr0 + rs0;
        lsum1 = lsum1 * corr1 + rs1;
        mrow0 = mn0;
        mrow1 = mn1;
#pragma unroll
        for (int nt = 0; nt < 8; nt++) {
            o[nt][0] *= corr0;
            o[nt][1] *= corr0;
            o[nt][2] *= corr1;
            o[nt][3] *= corr1;
        }

        // ---- store P as fp16 (warp-private rows) ----
#pragma unroll
        for (int nt = 0; nt < 8; nt++) {
            __half2 p0 = __float22half2_rn(make_float2(s[nt][0], s[nt][1]));
            __half2 p1 = __float22half2_rn(make_float2(s[nt][2], s[nt][3]));
            const int col = nt * 8 + 2 * lq;
            *(uint32_t*)&Ps[(wid * 16 + lr) * ST + col]     = *(uint32_t*)&p0;
            *(uint32_t*)&Ps[(wid * 16 + lr + 8) * ST + col] = *(uint32_t*)&p1;
        }
        __syncwarp();

        // ---- O += P V (fp16, 4 k16 steps; V via ldmatrix.trans) ----
#pragma unroll
        for (int step = 0; step < 4; step++) {
            uint32_t pf[4];
            ldsm4(pf, psU + (uint32_t)(p_row * ST + step * 16 + p_col) * 2);
#pragma unroll
            for (int np = 0; np < 4; np++) {
                uint32_t bb[4];
                ldsm4t(bb, vsU + (uint32_t)((step * 16 + vb_row) * ST + np * 16 + vb_col) * 2);
                mma_f16(o[2 * np],     pf, bb[0], bb[1]);
                mma_f16(o[2 * np + 1], pf, bb[2], bb[3]);
            }
        }
    }

    // write ctx as fp16 [B*S, H*64]
    const int b = bh >> 4;
    const int h = bh & 15;
    const float inv0 = 1.f / lsum0;
    const float inv1 = 1.f / lsum1;
    const int srow = qt * 128 + wid * 16 + lr;
#pragma unroll
    for (int nt = 0; nt < 8; nt++) {
        const int d = nt * 8 + 2 * lq;
        __half2 p0 = __float22half2_rn(make_float2(o[nt][0] * inv0, o[nt][1] * inv0));
        __half2 p1 = __float22half2_rn(make_float2(o[nt][2] * inv1, o[nt][3] * inv1));
        *(uint32_t*)&ctx[(size_t)(b * NS + srow) * NDM + h * 64 + d] = *(uint32_t*)&p0;
        *(uint32_t*)&ctx[(size_t)(b * NS + srow + 8) * NDM + h * 64 + d] = *(uint32_t*)&p1;
    }
}

// ---------------------------------------------------------------------------
// Fused residual + LayerNorm (in-place on out)
// ---------------------------------------------------------------------------
__global__ __launch_bounds__(256) void ln_kernel(const float* __restrict__ Qin,
                                                 const float* __restrict__ gamma,
                                                 const float* __restrict__ beta,
                                                 float* __restrict__ out) {
    __shared__ float rs[8], rq[8], fin[2];
    const int row = blockIdx.x;
    const int tid = threadIdx.x;
    const int c   = tid << 2;

    float4 o4 = *(const float4*)(out + (size_t)row * NDM + c);
    float4 q4 = *(const float4*)(Qin + (size_t)row * NDM + c);
    const float x0 = o4.x + q4.x, x1 = o4.y + q4.y, x2 = o4.z + q4.z, x3 = o4.w + q4.w;
    float s  = x0 + x1 + x2 + x3;
    float sq = x0 * x0 + x1 * x1 + x2 * x2 + x3 * x3;
#pragma unroll
    for (int off = 16; off; off >>= 1) {
        s  += __shfl_xor_sync(0xffffffffu, s, off);
        sq += __shfl_xor_sync(0xffffffffu, sq, off);
    }
    const int wid = tid >> 5, lane = tid & 31;
    if (lane == 0) { rs[wid] = s; rq[wid] = sq; }
    __syncthreads();
    if (tid == 0) {
        float a = 0.f, b2 = 0.f;
#pragma unroll
        for (int i = 0; i < 8; i++) { a += rs[i]; b2 += rq[i]; }
        fin[0] = a;
        fin[1] = b2;
    }
    __syncthreads();
    const float mu   = fin[0] * (1.0f / NDM);
    const float var  = fin[1] * (1.0f / NDM) - mu * mu;
    const float rstd = rsqrtf(var + 1e-5f);

    float4 g4 = *(const float4*)(gamma + c);
    float4 b4 = *(const float4*)(beta + c);
    float4 r;
    r.x = (x0 - mu) * rstd * g4.x + b4.x;
    r.y = (x1 - mu) * rstd * g4.y + b4.y;
    r.z = (x2 - mu) * rstd * g4.z + b4.z;
    r.w = (x3 - mu) * rstd * g4.w + b4.w;
    *(float4*)(out + (size_t)row * NDM + c) = r;
}

// ---------------------------------------------------------------------------
// Launch
// ---------------------------------------------------------------------------
extern "C" void kernel_launch(void* const* d_in, const int* in_sizes, int n_in,
                              void* d_out, int out_size) {
    const float* Q     = (const float*)d_in[0];
    const float* K     = (const float*)d_in[1];
    const float* V     = (const float*)d_in[2];
    const float* W_Q   = (const float*)d_in[3];
    const float* W_K   = (const float*)d_in[4];
    const float* W_V   = (const float*)d_in[5];
    const float* W_O   = (const float*)d_in[6];
    const float* gamma = (const float*)d_in[7];
    const float* beta  = (const float*)d_in[8];
    float* out = (float*)d_out;

    __half *qh, *kh, *vh, *ctxh, *qb, *kb, *vb, *wtq, *wtk, *wtv, *wto;
    cudaGetSymbolAddress((void**)&qh,   g_Qh);
    cudaGetSymbolAddress((void**)&kh,   g_Kh);
    cudaGetSymbolAddress((void**)&vh,   g_Vh);
    cudaGetSymbolAddress((void**)&ctxh, g_ctxh);
    cudaGetSymbolAddress((void**)&qb,   g_Qb);
    cudaGetSymbolAddress((void**)&kb,   g_Kb);
    cudaGetSymbolAddress((void**)&vb,   g_Vb);
    cudaGetSymbolAddress((void**)&wtq,  g_WTq);
    cudaGetSymbolAddress((void**)&wtk,  g_WTk);
    cudaGetSymbolAddress((void**)&wtv,  g_WTv);
    cudaGetSymbolAddress((void**)&wto,  g_WTo);

    cudaFuncSetAttribute(attn_h, cudaFuncAttributeMaxDynamicSharedMemorySize,
                         ATTN_SMEM_BYTES);

    const int convBlocks = NM * NDM / (256 * 4);   // 8192
    const dim3 tb(32, 32);

    // conversions
    f2h_kernel<<<convBlocks, 256>>>(Q, qb);
    f2h_kernel<<<convBlocks, 256>>>(K, kb);
    f2h_kernel<<<convBlocks, 256>>>(V, vb);
    wtrans_kernel<<<tb, 256>>>(W_Q, wtq);
    wtrans_kernel<<<tb, 256>>>(W_K, wtk);
    wtrans_kernel<<<tb, 256>>>(W_V, wtv);
    wtrans_kernel<<<tb, 256>>>(W_O, wto);

    // projections (fp16 heads)
    const dim3 gg(NDM / 128, NM / 128);   // (8, 64)
    gemm_h<2><<<gg, 256>>>(qb, wtq, qh);
    gemm_h<2><<<gg, 256>>>(kb, wtk, kh);
    gemm_h<2><<<gg, 256>>>(vb, wtv, vh);

    // attention (fully fp16), writes fp16 ctx
    attn_h<<<dim3(NS / 128, NB * NH), 256, ATTN_SMEM_BYTES>>>(qh, kh, vh, ctxh);

    // output projection + residual LN
    gemm_h<0><<<gg, 256>>>(ctxh, wto, out);
    ln_kernel<<<NM, 256>>>(Q, gamma, beta, out);
}

// round 7
// speedup vs baseline: 6.1496x; 1.0481x over previous
#include <cuda_runtime.h>
#include <cuda_fp16.h>
#include <cstdint>

// Problem constants
#define NB   4
#define NS   2048
#define NDM  1024
#define NH   16
#define NM   (NB * NS)      // 8192 rows

// ---------------------------------------------------------------------------
// Device scratch
// ---------------------------------------------------------------------------
__device__ __half g_Qh[NB * NH * NS * 64];   // fp16 heads [B,H,S,64]
__device__ __half g_Kh[NB * NH * NS * 64];
__device__ __half g_Vh[NB * NH * NS * 64];
__device__ __half g_ctxh[NM * NDM];          // fp16 ctx [B*S, H*Dv]

__device__ __half g_Qb[NM * NDM];            // fp16 activations [m][k]
__device__ __half g_Kb[NM * NDM];
__device__ __half g_Vb[NM * NDM];
__device__ __half g_WTq[NDM * NDM];          // fp16 W^T [n][k]
__device__ __half g_WTk[NDM * NDM];
__device__ __half g_WTv[NDM * NDM];
__device__ __half g_WTo[NDM * NDM];

// ---------------------------------------------------------------------------
// mma / ldmatrix / cp.async helpers
// ---------------------------------------------------------------------------
__device__ __forceinline__ uint32_t smem_u32(const void* p) {
    uint32_t a;
    asm("{ .reg .u64 t; cvta.to.shared.u64 t, %1; cvt.u32.u64 %0, t; }"
        : "=r"(a) : "l"(p));
    return a;
}

__device__ __forceinline__ void ldsm4(uint32_t r[4], uint32_t addr) {
    asm volatile("ldmatrix.sync.aligned.m8n8.x4.shared.b16 {%0,%1,%2,%3}, [%4];"
                 : "=r"(r[0]), "=r"(r[1]), "=r"(r[2]), "=r"(r[3]) : "r"(addr));
}

__device__ __forceinline__ void ldsm4t(uint32_t r[4], uint32_t addr) {
    asm volatile("ldmatrix.sync.aligned.m8n8.x4.trans.shared.b16 {%0,%1,%2,%3}, [%4];"
                 : "=r"(r[0]), "=r"(r[1]), "=r"(r[2]), "=r"(r[3]) : "r"(addr));
}

__device__ __forceinline__ void mma_f16(float c[4], const uint32_t a[4],
                                        uint32_t b0, uint32_t b1) {
    asm volatile(
        "mma.sync.aligned.m16n8k16.row.col.f32.f16.f16.f32 "
        "{%0,%1,%2,%3}, {%4,%5,%6,%7}, {%8,%9}, {%0,%1,%2,%3};"
        : "+f"(c[0]), "+f"(c[1]), "+f"(c[2]), "+f"(c[3])
        : "r"(a[0]), "r"(a[1]), "r"(a[2]), "r"(a[3]), "r"(b0), "r"(b1));
}

__device__ __forceinline__ void cp16(uint32_t dst, const void* src) {
    asm volatile("cp.async.cg.shared.global [%0], [%1], 16;" :: "r"(dst), "l"(src));
}
#define CP_COMMIT() asm volatile("cp.async.commit_group;")
#define CP_WAIT0()  asm volatile("cp.async.wait_group 0;")

// ---------------------------------------------------------------------------
// Batched conversion kernels
// ---------------------------------------------------------------------------
__global__ __launch_bounds__(256) void f2h3_kernel(const float* __restrict__ i0,
                                                   const float* __restrict__ i1,
                                                   const float* __restrict__ i2,
                                                   __half* o0, __half* o1, __half* o2) {
    const float* in = (blockIdx.y == 0) ? i0 : (blockIdx.y == 1) ? i1 : i2;
    __half* out = (blockIdx.y == 0) ? o0 : (blockIdx.y == 1) ? o1 : o2;
    const int i = (blockIdx.x * 256 + threadIdx.x) * 4;
    float4 v = *(const float4*)(in + i);
    __half2 a = __float22half2_rn(make_float2(v.x, v.y));
    __half2 b = __float22half2_rn(make_float2(v.z, v.w));
    uint2 u;
    u.x = *(uint32_t*)&a;
    u.y = *(uint32_t*)&b;
    *(uint2*)(out + i) = u;
}

// 4x W [k][n] fp32 -> WT [n][k] fp16 (tiled transpose), batched over z
__global__ __launch_bounds__(256) void wtrans4_kernel(const float* __restrict__ w0,
                                                      const float* __restrict__ w1,
                                                      const float* __restrict__ w2,
                                                      const float* __restrict__ w3,
                                                      __half* t0, __half* t1,
                                                      __half* t2, __half* t3) {
    __shared__ float t[32][33];
    const int z = blockIdx.z;
    const float* W = (z == 0) ? w0 : (z == 1) ? w1 : (z == 2) ? w2 : w3;
    __half* WT = (z == 0) ? t0 : (z == 1) ? t1 : (z == 2) ? t2 : t3;
    const int tx = threadIdx.x & 31;
    const int ty = threadIdx.x >> 5;
    const int bn = blockIdx.x * 32;
    const int bk = blockIdx.y * 32;
#pragma unroll
    for (int i = 0; i < 4; i++)
        t[ty + 8 * i][tx] = W[(size_t)(bk + ty + 8 * i) * NDM + bn + tx];
    __syncthreads();
#pragma unroll
    for (int i = 0; i < 4; i++)
        WT[(size_t)(bn + ty + 8 * i) * NDM + bk + tx] =
            __float2half(t[tx][ty + 8 * i]);
}

// ---------------------------------------------------------------------------
// fp16 mma.sync GEMM body (ldmatrix + 2-stage smem pipeline)
// BM=128, BN=128, BK=32; 8 warps, warp tile 32x64.
// MODE 0: fp32 [m][1024]; MODE 2: fp16 heads [B,H,S,64].
// ---------------------------------------------------------------------------
#define GW 20   // 32-bit words per smem row
#define GSTAGE (128 * GW * 4)

template <int MODE>
__device__ __forceinline__ void gemm_body(const __half* __restrict__ A,
                                          const __half* __restrict__ BT,
                                          void* __restrict__ Cv,
                                          uint32_t (*As)[128 * GW],
                                          uint32_t (*Bs)[128 * GW]) {
    const int tid  = threadIdx.x;
    const int lane = tid & 31;
    const int wid  = tid >> 5;
    const int lr   = lane >> 2;
    const int lq   = lane & 3;
    const int wm0  = (wid & 3) * 32;
    const int wn0  = (wid >> 2) * 64;
    const int m0   = blockIdx.y * 128;
    const int n0   = blockIdx.x * 128;

    const uint32_t AsU = smem_u32(As);
    const uint32_t BsU = smem_u32(Bs);

    const int a_row = wm0 + (lane & 7) + (lane & 8);
    const int a_wrd = (lane >> 4) << 2;
    const int b_row = wn0 + (lane & 7) + ((lane & 16) >> 1);
    const int b_wrd = (lane & 8) ? 4 : 0;

    const int r0 = tid >> 2;
    const int cu = tid & 3;
    const uint8_t* Ag = (const uint8_t*)A + (size_t)m0 * 2048 + cu * 16;
    const uint8_t* Bg = (const uint8_t*)BT + (size_t)n0 * 2048 + cu * 16;

    uint4 ra[2], rb[2];
#pragma unroll
    for (int i = 0; i < 2; i++) {
        ra[i] = *(const uint4*)(Ag + (size_t)(r0 + 64 * i) * 2048);
        rb[i] = *(const uint4*)(Bg + (size_t)(r0 + 64 * i) * 2048);
    }

    float acc[2][8][4];
#pragma unroll
    for (int mi = 0; mi < 2; mi++)
#pragma unroll
        for (int nt = 0; nt < 8; nt++)
#pragma unroll
            for (int v = 0; v < 4; v++) acc[mi][nt][v] = 0.f;

#pragma unroll
    for (int i = 0; i < 2; i++) {
        const int off = (r0 + 64 * i) * GW + cu * 4;
        *(uint4*)&As[0][off] = ra[i];
        *(uint4*)&Bs[0][off] = rb[i];
    }
    __syncthreads();

    for (int c = 0; c < 32; c++) {
        const int st = c & 1;
        if (c < 31) {
            const size_t koff = (size_t)(c + 1) * 64;
#pragma unroll
            for (int i = 0; i < 2; i++) {
                ra[i] = *(const uint4*)(Ag + (size_t)(r0 + 64 * i) * 2048 + koff);
                rb[i] = *(const uint4*)(Bg + (size_t)(r0 + 64 * i) * 2048 + koff);
            }
        }

#pragma unroll
        for (int s = 0; s < 2; s++) {
            uint32_t a[2][4];
            ldsm4(a[0], AsU + st * GSTAGE + ((a_row)*GW + s * 8 + a_wrd) * 4);
            ldsm4(a[1], AsU + st * GSTAGE + ((a_row + 16) * GW + s * 8 + a_wrd) * 4);
#pragma unroll
            for (int np = 0; np < 4; np++) {
                uint32_t bb[4];
                ldsm4(bb, BsU + st * GSTAGE + ((b_row + np * 16) * GW + s * 8 + b_wrd) * 4);
                mma_f16(acc[0][2 * np],     a[0], bb[0], bb[1]);
                mma_f16(acc[1][2 * np],     a[1], bb[0], bb[1]);
                mma_f16(acc[0][2 * np + 1], a[0], bb[2], bb[3]);
                mma_f16(acc[1][2 * np + 1], a[1], bb[2], bb[3]);
            }
        }

        if (c < 31) {
            const int st2 = st ^ 1;
#pragma unroll
            for (int i = 0; i < 2; i++) {
                const int off = (r0 + 64 * i) * GW + cu * 4;
                *(uint4*)&As[st2][off] = ra[i];
                *(uint4*)&Bs[st2][off] = rb[i];
            }
            __syncthreads();
        }
    }

#pragma unroll
    for (int mi = 0; mi < 2; mi++) {
        const int row0 = m0 + wm0 + mi * 16 + lr;
#pragma unroll
        for (int nt = 0; nt < 8; nt++) {
            const int col = wn0 + nt * 8 + 2 * lq;
            if (MODE == 2) {
                __half* C = (__half*)Cv;
                __half2 v0 = __float22half2_rn(make_float2(acc[mi][nt][0], acc[mi][nt][1]));
                __half2 v1 = __float22half2_rn(make_float2(acc[mi][nt][2], acc[mi][nt][3]));
                const int gcol = n0 + col;
                const int h = gcol >> 6, d = gcol & 63;
                const int b0i = row0 >> 11, s0 = row0 & 2047;
                *(uint32_t*)&C[(size_t)((b0i * NH + h) * NS + s0) * 64 + d] = *(uint32_t*)&v0;
                const int row1 = row0 + 8;
                const int b1i = row1 >> 11, s1 = row1 & 2047;
                *(uint32_t*)&C[(size_t)((b1i * NH + h) * NS + s1) * 64 + d] = *(uint32_t*)&v1;
            } else {
                float* C = (float*)Cv;
                *(float2*)&C[(size_t)row0 * NDM + n0 + col] =
                    make_float2(acc[mi][nt][0], acc[mi][nt][1]);
                *(float2*)&C[(size_t)(row0 + 8) * NDM + n0 + col] =
                    make_float2(acc[mi][nt][2], acc[mi][nt][3]);
            }
        }
    }
}

// Fused QKV projection: blockIdx.z selects (A, W^T, C) triple.
__global__ __launch_bounds__(256) void gemm_qkv(const __half* qb, const __half* kb,
                                                const __half* vb, const __half* wtq,
                                                const __half* wtk, const __half* wtv,
                                                __half* qh, __half* kh, __half* vh) {
    __shared__ __align__(16) uint32_t As[2][128 * GW];
    __shared__ __align__(16) uint32_t Bs[2][128 * GW];
    const int z = blockIdx.z;
    const __half* A  = (z == 0) ? qb : (z == 1) ? kb : vb;
    const __half* BT = (z == 0) ? wtq : (z == 1) ? wtk : wtv;
    __half* C        = (z == 0) ? qh : (z == 1) ? kh : vh;
    gemm_body<2>(A, BT, C, As, Bs);
}

// Output projection: fp32 row-major out.
__global__ __launch_bounds__(256) void gemm_out(const __half* __restrict__ A,
                                                const __half* __restrict__ BT,
                                                float* __restrict__ C) {
    __shared__ __align__(16) uint32_t As[2][128 * GW];
    __shared__ __align__(16) uint32_t Bs[2][128 * GW];
    gemm_body<0>(A, BT, C, As, Bs);
}

// ---------------------------------------------------------------------------
// Flash attention, causal, fp16 mma m16n8k16, cp.async double-buffered K/V.
// Q tile 128, K tile 64. 8 warps; warp w owns q-rows [16w,16w+16).
// ---------------------------------------------------------------------------
#define ST 72   // halves per smem row
// Qs[128][ST] + Ks[2][64][ST] + Vs[2][64][ST] + Ps[128][ST]
#define ATTN_SMEM_BYTES ((128 + 2 * 64 + 2 * 64 + 128) * ST * 2)   // 73728

__global__ __launch_bounds__(256) void attn_h(const __half* __restrict__ Qh,
                                              const __half* __restrict__ Kh,
                                              const __half* __restrict__ Vh,
                                              __half* __restrict__ ctx) {
    extern __shared__ __half smh[];
    __half* Qs = smh;                         // [128][ST]
    __half* Ks0 = Qs + 128 * ST;              // [2][64][ST]
    __half* Vs0 = Ks0 + 2 * 64 * ST;          // [2][64][ST]
    __half* Ps = Vs0 + 2 * 64 * ST;           // [128][ST]
    const uint32_t qsU = smem_u32(Qs);
    const uint32_t ksU = smem_u32(Ks0);
    const uint32_t vsU = smem_u32(Vs0);
    const uint32_t psU = smem_u32(Ps);
    const uint32_t KVSTG = 64 * ST * 2;       // bytes per stage

    const int tid  = threadIdx.x;
    const int lane = tid & 31;
    const int wid  = tid >> 5;
    const int lr   = lane >> 2;
    const int lq   = lane & 3;

    const int qt = gridDim.x - 1 - blockIdx.x;   // heavy tiles first
    const int bh = blockIdx.y;

    const __half* Qb = Qh + (size_t)bh * NS * 64;
    const __half* Kb = Kh + (size_t)bh * NS * 64;
    const __half* Vb = Vh + (size_t)bh * NS * 64;

    // cp.async fill mapping: 2 x 16B per thread for each of K and V
    const int fr = tid >> 2;           // 0..63 (rows, two chunks of 32... )
    // use idx = tid + 256*i -> r = idx>>3, cu = idx&7
    // prefetch tile kt into stage st
    auto prefetch = [&](int kt, int st) {
#pragma unroll
        for (int i = 0; i < 2; i++) {
            const int idx = tid + 256 * i;
            const int r = idx >> 3, cu = idx & 7;
            cp16(ksU + (uint32_t)st * KVSTG + (uint32_t)(r * ST + cu * 8) * 2,
                 Kb + (size_t)(kt * 64 + r) * 64 + cu * 8);
            cp16(vsU + (uint32_t)st * KVSTG + (uint32_t)(r * ST + cu * 8) * 2,
                 Vb + (size_t)(kt * 64 + r) * 64 + cu * 8);
        }
        CP_COMMIT();
    };
    (void)fr;

    // Load Q tile (128 x 64 fp16) coalesced + prefetch kt=0
    prefetch(0, 0);
#pragma unroll
    for (int i = 0; i < 4; i++) {
        const int idx = tid + 256 * i;
        const int r = idx >> 3, cu = idx & 7;
        *(uint4*)&Qs[r * ST + cu * 8] =
            *(const uint4*)(Qb + (size_t)(qt * 128 + r) * 64 + cu * 8);
    }
    __syncthreads();

    // Hoist Q fragments to registers (A operand, 4 k16 steps)
    uint32_t qf[4][4];
    {
        const int arow = wid * 16 + (lane & 7) + (lane & 8);
        const int acol = (lane & 16) >> 1;
#pragma unroll
        for (int s = 0; s < 4; s++)
            ldsm4(qf[s], qsU + (uint32_t)(arow * ST + s * 16 + acol) * 2);
    }

    float o[8][4];
#pragma unroll
    for (int nt = 0; nt < 8; nt++)
#pragma unroll
        for (int v = 0; v < 4; v++) o[nt][v] = 0.f;
    float mrow0 = -1e30f, mrow1 = -1e30f, lsum0 = 0.f, lsum1 = 0.f;

    const int qrow0 = qt * 128 + wid * 16 + lr;
    const int qrow1 = qrow0 + 8;
    const int ktmax = 2 * qt + 1;

    const int kb_row = (lane & 7) + ((lane & 16) >> 1);
    const int kb_col = (lane & 8) ? 8 : 0;
    const int vb_row = (lane & 7) + (lane & 8);
    const int vb_col = (lane & 16) >> 1;
    const int p_row  = wid * 16 + (lane & 7) + (lane & 8);
    const int p_col  = (lane & 16) >> 1;

    for (int kt = 0; kt <= ktmax; kt++) {
        const int st = kt & 1;
        CP_WAIT0();
        __syncthreads();   // stage st ready; stage st^1 free (all reads done)
        if (kt < ktmax) prefetch(kt + 1, st ^ 1);

        const uint32_t kBase = ksU + (uint32_t)st * KVSTG;
        const uint32_t vBase = vsU + (uint32_t)st * KVSTG;

        // ---- S = Q K^T (fp16, 4 k16 steps) ----
        float s[8][4];
#pragma unroll
        for (int nt = 0; nt < 8; nt++)
#pragma unroll
            for (int v = 0; v < 4; v++) s[nt][v] = 0.f;

#pragma unroll
        for (int step = 0; step < 4; step++) {
#pragma unroll
            for (int np = 0; np < 4; np++) {
                uint32_t bb[4];
                ldsm4(bb, kBase + (uint32_t)((np * 16 + kb_row) * ST + step * 16 + kb_col) * 2);
                mma_f16(s[2 * np],     qf[step], bb[0], bb[1]);
                mma_f16(s[2 * np + 1], qf[step], bb[2], bb[3]);
            }
        }

        // scale + causal mask
        const bool diag = (kt >= 2 * qt);
#pragma unroll
        for (int nt = 0; nt < 8; nt++) {
            const int col = kt * 64 + nt * 8 + 2 * lq;
            s[nt][0] *= 0.125f;
            s[nt][1] *= 0.125f;
            s[nt][2] *= 0.125f;
            s[nt][3] *= 0.125f;
            if (diag) {
                if (col     > qrow0) s[nt][0] = -1e30f;
                if (col + 1 > qrow0) s[nt][1] = -1e30f;
                if (col     > qrow1) s[nt][2] = -1e30f;
                if (col + 1 > qrow1) s[nt][3] = -1e30f;
            }
        }

        // ---- online softmax ----
        float mx0 = -1e30f, mx1 = -1e30f;
#pragma unroll
        for (int nt = 0; nt < 8; nt++) {
            mx0 = fmaxf(mx0, fmaxf(s[nt][0], s[nt][1]));
            mx1 = fmaxf(mx1, fmaxf(s[nt][2], s[nt][3]));
        }
        mx0 = fmaxf(mx0, __shfl_xor_sync(0xffffffffu, mx0, 1));
        mx0 = fmaxf(mx0, __shfl_xor_sync(0xffffffffu, mx0, 2));
        mx1 = fmaxf(mx1, __shfl_xor_sync(0xffffffffu, mx1, 1));
        mx1 = fmaxf(mx1, __shfl_xor_sync(0xffffffffu, mx1, 2));

        const float mn0 = fmaxf(mrow0, mx0);
        const float mn1 = fmaxf(mrow1, mx1);
        const float corr0 = __expf(mrow0 - mn0);
        const float corr1 = __expf(mrow1 - mn1);

        float rs0 = 0.f, rs1 = 0.f;
#pragma unroll
        for (int nt = 0; nt < 8; nt++) {
            s[nt][0] = __expf(s[nt][0] - mn0);
            s[nt][1] = __expf(s[nt][1] - mn0);
            s[nt][2] = __expf(s[nt][2] - mn1);
            s[nt][3] = __expf(s[nt][3] - mn1);
            rs0 += s[nt][0] + s[nt][1];
            rs1 += s[nt][2] + s[nt][3];
        }
        rs0 += __shfl_xor_sync(0xffffffffu, rs0, 1);
        rs0 += __shfl_xor_sync(0xffffffffu, rs0, 2);
        rs1 += __shfl_xor_sync(0xffffffffu, rs1, 1);
        rs1 += __shfl_xor_sync(0xffffffffu, rs1, 2);

        lsum0 = lsum0 * corr0 + rs0;
        lsum1 = lsum1 * corr1 + rs1;
        mrow0 = mn0;
        mrow1 = mn1;
#pragma unroll
        for (int nt = 0; nt < 8; nt++) {
            o[nt][0] *= corr0;
            o[nt][1] *= corr0;
            o[nt][2] *= corr1;
            o[nt][3] *= corr1;
        }

        // ---- store P as fp16 (warp-private rows) ----
#pragma unroll
        for (int nt = 0; nt < 8; nt++) {
            __half2 p0 = __float22half2_rn(make_float2(s[nt][0], s[nt][1]));
            __half2 p1 = __float22half2_rn(make_float2(s[nt][2], s[nt][3]));
            const int col = nt * 8 + 2 * lq;
            *(uint32_t*)&Ps[(wid * 16 + lr) * ST + col]     = *(uint32_t*)&p0;
            *(uint32_t*)&Ps[(wid * 16 + lr + 8) * ST + col] = *(uint32_t*)&p1;
        }
        __syncwarp();

        // ---- O += P V (fp16, 4 k16 steps; V via ldmatrix.trans) ----
#pragma unroll
        for (int step = 0; step < 4; step++) {
            uint32_t pf[4];
            ldsm4(pf, psU + (uint32_t)(p_row * ST + step * 16 + p_col) * 2);
#pragma unroll
            for (int np = 0; np < 4; np++) {
                uint32_t bb[4];
                ldsm4t(bb, vBase + (uint32_t)((step * 16 + vb_row) * ST + np * 16 + vb_col) * 2);
                mma_f16(o[2 * np],     pf, bb[0], bb[1]);
                mma_f16(o[2 * np + 1], pf, bb[2], bb[3]);
            }
        }
    }

    // write ctx as fp16 [B*S, H*64]
    const int b = bh >> 4;
    const int h = bh & 15;
    const float inv0 = 1.f / lsum0;
    const float inv1 = 1.f / lsum1;
    const int srow = qt * 128 + wid * 16 + lr;
#pragma unroll
    for (int nt = 0; nt < 8; nt++) {
        const int d = nt * 8 + 2 * lq;
        __half2 p0 = __float22half2_rn(make_float2(o[nt][0] * inv0, o[nt][1] * inv0));
        __half2 p1 = __float22half2_rn(make_float2(o[nt][2] * inv1, o[nt][3] * inv1));
        *(uint32_t*)&ctx[(size_t)(b * NS + srow) * NDM + h * 64 + d] = *(uint32_t*)&p0;
        *(uint32_t*)&ctx[(size_t)(b * NS + srow + 8) * NDM + h * 64 + d] = *(uint32_t*)&p1;
    }
}

// ---------------------------------------------------------------------------
// Fused residual + LayerNorm (in-place on out)
// ---------------------------------------------------------------------------
__global__ __launch_bounds__(256) void ln_kernel(const float* __restrict__ Qin,
                                                 const float* __restrict__ gamma,
                                                 const float* __restrict__ beta,
                                                 float* __restrict__ out) {
    __shared__ float rs[8], rq[8], fin[2];
    const int row = blockIdx.x;
    const int tid = threadIdx.x;
    const int c   = tid << 2;

    float4 o4 = *(const float4*)(out + (size_t)row * NDM + c);
    float4 q4 = *(const float4*)(Qin + (size_t)row * NDM + c);
    const float x0 = o4.x + q4.x, x1 = o4.y + q4.y, x2 = o4.z + q4.z, x3 = o4.w + q4.w;
    float s  = x0 + x1 + x2 + x3;
    float sq = x0 * x0 + x1 * x1 + x2 * x2 + x3 * x3;
#pragma unroll
    for (int off = 16; off; off >>= 1) {
        s  += __shfl_xor_sync(0xffffffffu, s, off);
        sq += __shfl_xor_sync(0xffffffffu, sq, off);
    }
    const int wid = tid >> 5, lane = tid & 31;
    if (lane == 0) { rs[wid] = s; rq[wid] = sq; }
    __syncthreads();
    if (tid == 0) {
        float a = 0.f, b2 = 0.f;
#pragma unroll
        for (int i = 0; i < 8; i++) { a += rs[i]; b2 += rq[i]; }
        fin[0] = a;
        fin[1] = b2;
    }
    __syncthreads();
    const float mu   = fin[0] * (1.0f / NDM);
    const float var  = fin[1] * (1.0f / NDM) - mu * mu;
    const float rstd = rsqrtf(var + 1e-5f);

    float4 g4 = *(const float4*)(gamma + c);
    float4 b4 = *(const float4*)(beta + c);
    float4 r;
    r.x = (x0 - mu) * rstd * g4.x + b4.x;
    r.y = (x1 - mu) * rstd * g4.y + b4.y;
    r.z = (x2 - mu) * rstd * g4.z + b4.z;
    r.w = (x3 - mu) * rstd * g4.w + b4.w;
    *(float4*)(out + (size_t)row * NDM + c) = r;
}

// ---------------------------------------------------------------------------
// Launch
// ---------------------------------------------------------------------------
extern "C" void kernel_launch(void* const* d_in, const int* in_sizes, int n_in,
                              void* d_out, int out_size) {
    const float* Q     = (const float*)d_in[0];
    const float* K     = (const float*)d_in[1];
    const float* V     = (const float*)d_in[2];
    const float* W_Q   = (const float*)d_in[3];
    const float* W_K   = (const float*)d_in[4];
    const float* W_V   = (const float*)d_in[5];
    const float* W_O   = (const float*)d_in[6];
    const float* gamma = (const float*)d_in[7];
    const float* beta  = (const float*)d_in[8];
    float* out = (float*)d_out;

    __half *qh, *kh, *vh, *ctxh, *qb, *kb, *vb, *wtq, *wtk, *wtv, *wto;
    cudaGetSymbolAddress((void**)&qh,   g_Qh);
    cudaGetSymbolAddress((void**)&kh,   g_Kh);
    cudaGetSymbolAddress((void**)&vh,   g_Vh);
    cudaGetSymbolAddress((void**)&ctxh, g_ctxh);
    cudaGetSymbolAddress((void**)&qb,   g_Qb);
    cudaGetSymbolAddress((void**)&kb,   g_Kb);
    cudaGetSymbolAddress((void**)&vb,   g_Vb);
    cudaGetSymbolAddress((void**)&wtq,  g_WTq);
    cudaGetSymbolAddress((void**)&wtk,  g_WTk);
    cudaGetSymbolAddress((void**)&wtv,  g_WTv);
    cudaGetSymbolAddress((void**)&wto,  g_WTo);

    cudaFuncSetAttribute(attn_h, cudaFuncAttributeMaxDynamicSharedMemorySize,
                         ATTN_SMEM_BYTES);

    // conversions (batched)
    f2h3_kernel<<<dim3(NM * NDM / 1024, 3), 256>>>(Q, K, V, qb, kb, vb);
    wtrans4_kernel<<<dim3(32, 32, 4), 256>>>(W_Q, W_K, W_V, W_O, wtq, wtk, wtv, wto);

    // QKV projections fused in one launch
    gemm_qkv<<<dim3(NDM / 128, NM / 128, 3), 256>>>(qb, kb, vb, wtq, wtk, wtv,
                                                    qh, kh, vh);

    // attention (fp16, cp.async double-buffered), writes fp16 ctx
    attn_h<<<dim3(NS / 128, NB * NH), 256, ATTN_SMEM_BYTES>>>(qh, kh, vh, ctxh);

    // output projection + residual LN
    gemm_out<<<dim3(NDM / 128, NM / 128), 256>>>(ctxh, wto, out);
    ln_kernel<<<NM, 256>>>(Q, gamma, beta, out);
}

// round 8
// speedup vs baseline: 6.8025x; 1.1062x over previous
#include <cuda_runtime.h>
#include <cuda_fp16.h>
#include <cstdint>

// Problem constants
#define NB   4
#define NS   2048
#define NDM  1024
#define NH   16
#define NM   (NB * NS)      // 8192 rows

// ---------------------------------------------------------------------------
// Device scratch
// ---------------------------------------------------------------------------
__device__ __half g_Qh[NB * NH * NS * 64];   // fp16 heads [B,H,S,64] (Q pre-scaled)
__device__ __half g_Kh[NB * NH * NS * 64];
__device__ __half g_Vh[NB * NH * NS * 64];
__device__ __half g_ctxh[NM * NDM];          // fp16 ctx [B*S, H*Dv]

__device__ __half g_Qb[NM * NDM];            // fp16 activations [m][k]
__device__ __half g_Kb[NM * NDM];
__device__ __half g_Vb[NM * NDM];
__device__ __half g_WTq[NDM * NDM];          // fp16 W^T [n][k]
__device__ __half g_WTk[NDM * NDM];
__device__ __half g_WTv[NDM * NDM];
__device__ __half g_WTo[NDM * NDM];

// scale folded into Q heads: 1/sqrt(64) * log2(e)
#define QSCALE 0.18033688011112042f

// ---------------------------------------------------------------------------
// mma / ldmatrix / cp.async helpers
// ---------------------------------------------------------------------------
__device__ __forceinline__ uint32_t smem_u32(const void* p) {
    uint32_t a;
    asm("{ .reg .u64 t; cvta.to.shared.u64 t, %1; cvt.u32.u64 %0, t; }"
        : "=r"(a) : "l"(p));
    return a;
}

__device__ __forceinline__ void ldsm4(uint32_t r[4], uint32_t addr) {
    asm volatile("ldmatrix.sync.aligned.m8n8.x4.shared.b16 {%0,%1,%2,%3}, [%4];"
                 : "=r"(r[0]), "=r"(r[1]), "=r"(r[2]), "=r"(r[3]) : "r"(addr));
}

__device__ __forceinline__ void ldsm4t(uint32_t r[4], uint32_t addr) {
    asm volatile("ldmatrix.sync.aligned.m8n8.x4.trans.shared.b16 {%0,%1,%2,%3}, [%4];"
                 : "=r"(r[0]), "=r"(r[1]), "=r"(r[2]), "=r"(r[3]) : "r"(addr));
}

__device__ __forceinline__ void mma_f16(float c[4], const uint32_t a[4],
                                        uint32_t b0, uint32_t b1) {
    asm volatile(
        "mma.sync.aligned.m16n8k16.row.col.f32.f16.f16.f32 "
        "{%0,%1,%2,%3}, {%4,%5,%6,%7}, {%8,%9}, {%0,%1,%2,%3};"
        : "+f"(c[0]), "+f"(c[1]), "+f"(c[2]), "+f"(c[3])
        : "r"(a[0]), "r"(a[1]), "r"(a[2]), "r"(a[3]), "r"(b0), "r"(b1));
}

__device__ __forceinline__ void cp16(uint32_t dst, const void* src) {
    asm volatile("cp.async.cg.shared.global [%0], [%1], 16;" :: "r"(dst), "l"(src));
}
#define CP_COMMIT() asm volatile("cp.async.commit_group;")
#define CP_WAIT0()  asm volatile("cp.async.wait_group 0;")
#define CP_WAIT2()  asm volatile("cp.async.wait_group 2;")

__device__ __forceinline__ float ex2(float x) {
    float r;
    asm("ex2.approx.f32 %0, %1;" : "=f"(r) : "f"(x));
    return r;
}

// ---------------------------------------------------------------------------
// Batched conversion kernels
// ---------------------------------------------------------------------------
__global__ __launch_bounds__(256) void f2h3_kernel(const float* __restrict__ i0,
                                                   const float* __restrict__ i1,
                                                   const float* __restrict__ i2,
                                                   __half* o0, __half* o1, __half* o2) {
    const float* in = (blockIdx.y == 0) ? i0 : (blockIdx.y == 1) ? i1 : i2;
    __half* out = (blockIdx.y == 0) ? o0 : (blockIdx.y == 1) ? o1 : o2;
    const int i = (blockIdx.x * 256 + threadIdx.x) * 4;
    float4 v = *(const float4*)(in + i);
    __half2 a = __float22half2_rn(make_float2(v.x, v.y));
    __half2 b = __float22half2_rn(make_float2(v.z, v.w));
    uint2 u;
    u.x = *(uint32_t*)&a;
    u.y = *(uint32_t*)&b;
    *(uint2*)(out + i) = u;
}

__global__ __launch_bounds__(256) void wtrans4_kernel(const float* __restrict__ w0,
                                                      const float* __restrict__ w1,
                                                      const float* __restrict__ w2,
                                                      const float* __restrict__ w3,
                                                      __half* t0, __half* t1,
                                                      __half* t2, __half* t3) {
    __shared__ float t[32][33];
    const int z = blockIdx.z;
    const float* W = (z == 0) ? w0 : (z == 1) ? w1 : (z == 2) ? w2 : w3;
    __half* WT = (z == 0) ? t0 : (z == 1) ? t1 : (z == 2) ? t2 : t3;
    const int tx = threadIdx.x & 31;
    const int ty = threadIdx.x >> 5;
    const int bn = blockIdx.x * 32;
    const int bk = blockIdx.y * 32;
#pragma unroll
    for (int i = 0; i < 4; i++)
        t[ty + 8 * i][tx] = W[(size_t)(bk + ty + 8 * i) * NDM + bn + tx];
    __syncthreads();
#pragma unroll
    for (int i = 0; i < 4; i++)
        WT[(size_t)(bn + ty + 8 * i) * NDM + bk + tx] =
            __float2half(t[tx][ty + 8 * i]);
}

// ---------------------------------------------------------------------------
// fp16 mma.sync GEMM body: 4-stage cp.async pipeline.
// BM=128, BN=128, BK=32; 8 warps, warp tile 32x64.
// MODE 0: fp32 [m][1024]; MODE 2: fp16 heads [B,H,S,64], scaled by `scale`.
// ---------------------------------------------------------------------------
#define GW 20                      // 32-bit words per smem row
#define GSTG 10240                 // bytes per (A or B) stage: 128*GW*4
#define GEMM_SMEM (4 * 2 * GSTG)   // 81920

template <int MODE>
__device__ __forceinline__ void gemm_body(const __half* __restrict__ A,
                                          const __half* __restrict__ BT,
                                          void* __restrict__ Cv, float scale) {
    extern __shared__ __align__(16) uint8_t gsm[];
    const uint32_t base = smem_u32(gsm);

    const int tid  = threadIdx.x;
    const int lane = tid & 31;
    const int wid  = tid >> 5;
    const int lr   = lane >> 2;
    const int lq   = lane & 3;
    const int wm0  = (wid & 3) * 32;
    const int wn0  = (wid >> 2) * 64;
    const int m0   = blockIdx.y * 128;
    const int n0   = blockIdx.x * 128;

    const int a_row = wm0 + (lane & 7) + (lane & 8);
    const int a_wrd = (lane >> 4) << 2;
    const int b_row = wn0 + (lane & 7) + ((lane & 16) >> 1);
    const int b_wrd = (lane & 8) ? 4 : 0;

    const int r0 = tid >> 2;
    const int cu = tid & 3;
    const uint8_t* Ag = (const uint8_t*)A + (size_t)m0 * 2048 + cu * 16;
    const uint8_t* Bg = (const uint8_t*)BT + (size_t)n0 * 2048 + cu * 16;

    auto prefetch = [&](int c) {
        const int stg = c & 3;
        const uint32_t aB = base + (uint32_t)stg * (2 * GSTG);
        const uint32_t bB = aB + GSTG;
        const size_t koff = (size_t)c * 64;
#pragma unroll
        for (int i = 0; i < 2; i++) {
            const uint32_t so = (uint32_t)((r0 + 64 * i) * GW + cu * 4) * 4;
            cp16(aB + so, Ag + (size_t)(r0 + 64 * i) * 2048 + koff);
            cp16(bB + so, Bg + (size_t)(r0 + 64 * i) * 2048 + koff);
        }
        CP_COMMIT();
    };

    float acc[2][8][4];
#pragma unroll
    for (int mi = 0; mi < 2; mi++)
#pragma unroll
        for (int nt = 0; nt < 8; nt++)
#pragma unroll
            for (int v = 0; v < 4; v++) acc[mi][nt][v] = 0.f;

    prefetch(0);
    prefetch(1);
    prefetch(2);

    for (int c = 0; c < 32; c++) {
        if (c < 29) CP_WAIT2(); else CP_WAIT0();
        __syncthreads();
        if (c + 3 < 32) prefetch(c + 3);

        const int stg = c & 3;
        const uint32_t aB = base + (uint32_t)stg * (2 * GSTG);
        const uint32_t bB = aB + GSTG;

#pragma unroll
        for (int s = 0; s < 2; s++) {
            uint32_t a[2][4];
            ldsm4(a[0], aB + (uint32_t)((a_row)*GW + s * 8 + a_wrd) * 4);
            ldsm4(a[1], aB + (uint32_t)((a_row + 16) * GW + s * 8 + a_wrd) * 4);
#pragma unroll
            for (int np = 0; np < 4; np++) {
                uint32_t bb[4];
                ldsm4(bb, bB + (uint32_t)((b_row + np * 16) * GW + s * 8 + b_wrd) * 4);
                mma_f16(acc[0][2 * np],     a[0], bb[0], bb[1]);
                mma_f16(acc[1][2 * np],     a[1], bb[0], bb[1]);
                mma_f16(acc[0][2 * np + 1], a[0], bb[2], bb[3]);
                mma_f16(acc[1][2 * np + 1], a[1], bb[2], bb[3]);
            }
        }
    }

#pragma unroll
    for (int mi = 0; mi < 2; mi++) {
        const int row0 = m0 + wm0 + mi * 16 + lr;
#pragma unroll
        for (int nt = 0; nt < 8; nt++) {
            const int col = wn0 + nt * 8 + 2 * lq;
            if (MODE == 2) {
                __half* C = (__half*)Cv;
                __half2 v0 = __float22half2_rn(
                    make_float2(acc[mi][nt][0] * scale, acc[mi][nt][1] * scale));
                __half2 v1 = __float22half2_rn(
                    make_float2(acc[mi][nt][2] * scale, acc[mi][nt][3] * scale));
                const int gcol = n0 + col;
                const int h = gcol >> 6, d = gcol & 63;
                const int b0i = row0 >> 11, s0 = row0 & 2047;
                *(uint32_t*)&C[(size_t)((b0i * NH + h) * NS + s0) * 64 + d] = *(uint32_t*)&v0;
                const int row1 = row0 + 8;
                const int b1i = row1 >> 11, s1 = row1 & 2047;
                *(uint32_t*)&C[(size_t)((b1i * NH + h) * NS + s1) * 64 + d] = *(uint32_t*)&v1;
            } else {
                float* C = (float*)Cv;
                *(float2*)&C[(size_t)row0 * NDM + n0 + col] =
                    make_float2(acc[mi][nt][0], acc[mi][nt][1]);
                *(float2*)&C[(size_t)(row0 + 8) * NDM + n0 + col] =
                    make_float2(acc[mi][nt][2], acc[mi][nt][3]);
            }
        }
    }
}

// Fused QKV projection: blockIdx.z selects (A, W^T, C, scale).
__global__ __launch_bounds__(256) void gemm_qkv(const __half* qb, const __half* kb,
                                                const __half* vb, const __half* wtq,
                                                const __half* wtk, const __half* wtv,
                                                __half* qh, __half* kh, __half* vh) {
    const int z = blockIdx.z;
    const __half* A  = (z == 0) ? qb : (z == 1) ? kb : vb;
    const __half* BT = (z == 0) ? wtq : (z == 1) ? wtk : wtv;
    __half* C        = (z == 0) ? qh : (z == 1) ? kh : vh;
    const float sc   = (z == 0) ? QSCALE : 1.0f;
    gemm_body<2>(A, BT, C, sc);
}

__global__ __launch_bounds__(256) void gemm_out(const __half* __restrict__ A,
                                                const __half* __restrict__ BT,
                                                float* __restrict__ C) {
    gemm_body<0>(A, BT, C, 1.0f);
}

// ---------------------------------------------------------------------------
// Flash attention, causal, fp16 mma m16n8k16.
// S accumulators feed PV directly as A-fragments (no P smem round trip).
// exp2-domain softmax (scale*log2e folded into Q).
// cp.async double-buffered K/V.
// ---------------------------------------------------------------------------
#define ST 72   // halves per smem row
// Qs[128][ST] + Ks[2][64][ST] + Vs[2][64][ST]
#define ATTN_SMEM_BYTES ((128 + 2 * 64 + 2 * 64) * ST * 2)   // 55296

__global__ __launch_bounds__(256) void attn_h(const __half* __restrict__ Qh,
                                              const __half* __restrict__ Kh,
                                              const __half* __restrict__ Vh,
                                              __half* __restrict__ ctx) {
    extern __shared__ __half smh[];
    __half* Qs = smh;                         // [128][ST]
    __half* Ks0 = Qs + 128 * ST;              // [2][64][ST]
    __half* Vs0 = Ks0 + 2 * 64 * ST;          // [2][64][ST]
    const uint32_t qsU = smem_u32(Qs);
    const uint32_t ksU = smem_u32(Ks0);
    const uint32_t vsU = smem_u32(Vs0);
    const uint32_t KVSTG = 64 * ST * 2;       // bytes per stage

    const int tid  = threadIdx.x;
    const int lane = tid & 31;
    const int wid  = tid >> 5;
    const int lr   = lane >> 2;
    const int lq   = lane & 3;

    const int qt = gridDim.x - 1 - blockIdx.x;   // heavy tiles first
    const int bh = blockIdx.y;

    const __half* Qb = Qh + (size_t)bh * NS * 64;
    const __half* Kb = Kh + (size_t)bh * NS * 64;
    const __half* Vb = Vh + (size_t)bh * NS * 64;

    auto prefetch = [&](int kt, int st) {
#pragma unroll
        for (int i = 0; i < 2; i++) {
            const int idx = tid + 256 * i;
            const int r = idx >> 3, cu = idx & 7;
            cp16(ksU + (uint32_t)st * KVSTG + (uint32_t)(r * ST + cu * 8) * 2,
                 Kb + (size_t)(kt * 64 + r) * 64 + cu * 8);
            cp16(vsU + (uint32_t)st * KVSTG + (uint32_t)(r * ST + cu * 8) * 2,
                 Vb + (size_t)(kt * 64 + r) * 64 + cu * 8);
        }
        CP_COMMIT();
    };

    prefetch(0, 0);
#pragma unroll
    for (int i = 0; i < 4; i++) {
        const int idx = tid + 256 * i;
        const int r = idx >> 3, cu = idx & 7;
        *(uint4*)&Qs[r * ST + cu * 8] =
            *(const uint4*)(Qb + (size_t)(qt * 128 + r) * 64 + cu * 8);
    }
    __syncthreads();

    uint32_t qf[4][4];
    {
        const int arow = wid * 16 + (lane & 7) + (lane & 8);
        const int acol = (lane & 16) >> 1;
#pragma unroll
        for (int s = 0; s < 4; s++)
            ldsm4(qf[s], qsU + (uint32_t)(arow * ST + s * 16 + acol) * 2);
    }

    float o[8][4];
#pragma unroll
    for (int nt = 0; nt < 8; nt++)
#pragma unroll
        for (int v = 0; v < 4; v++) o[nt][v] = 0.f;
    float mrow0 = -1e30f, mrow1 = -1e30f, lsum0 = 0.f, lsum1 = 0.f;

    const int qrow0 = qt * 128 + wid * 16 + lr;
    const int qrow1 = qrow0 + 8;
    const int ktmax = 2 * qt + 1;

    const int kb_row = (lane & 7) + ((lane & 16) >> 1);
    const int kb_col = (lane & 8) ? 8 : 0;
    const int vb_row = (lane & 7) + (lane & 8);
    const int vb_col = (lane & 16) >> 1;

    for (int kt = 0; kt <= ktmax; kt++) {
        const int st = kt & 1;
        CP_WAIT0();
        __syncthreads();
        if (kt < ktmax) prefetch(kt + 1, st ^ 1);

        const uint32_t kBase = ksU + (uint32_t)st * KVSTG;
        const uint32_t vBase = vsU + (uint32_t)st * KVSTG;

        // ---- S = Q K^T (scores already in log2 domain via QSCALE) ----
        float s[8][4];
#pragma unroll
        for (int nt = 0; nt < 8; nt++)
#pragma unroll
            for (int v = 0; v < 4; v++) s[nt][v] = 0.f;

#pragma unroll
        for (int step = 0; step < 4; step++) {
#pragma unroll
            for (int np = 0; np < 4; np++) {
                uint32_t bb[4];
                ldsm4(bb, kBase + (uint32_t)((np * 16 + kb_row) * ST + step * 16 + kb_col) * 2);
                mma_f16(s[2 * np],     qf[step], bb[0], bb[1]);
                mma_f16(s[2 * np + 1], qf[step], bb[2], bb[3]);
            }
        }

        // causal mask (diagonal tiles only)
        if (kt >= 2 * qt) {
#pragma unroll
            for (int nt = 0; nt < 8; nt++) {
                const int col = kt * 64 + nt * 8 + 2 * lq;
                if (col     > qrow0) s[nt][0] = -1e30f;
                if (col + 1 > qrow0) s[nt][1] = -1e30f;
                if (col     > qrow1) s[nt][2] = -1e30f;
                if (col + 1 > qrow1) s[nt][3] = -1e30f;
            }
        }

        // ---- online softmax (log2 domain) ----
        float mx0 = -1e30f, mx1 = -1e30f;
#pragma unroll
        for (int nt = 0; nt < 8; nt++) {
            mx0 = fmaxf(mx0, fmaxf(s[nt][0], s[nt][1]));
            mx1 = fmaxf(mx1, fmaxf(s[nt][2], s[nt][3]));
        }
        mx0 = fmaxf(mx0, __shfl_xor_sync(0xffffffffu, mx0, 1));
        mx0 = fmaxf(mx0, __shfl_xor_sync(0xffffffffu, mx0, 2));
        mx1 = fmaxf(mx1, __shfl_xor_sync(0xffffffffu, mx1, 1));
        mx1 = fmaxf(mx1, __shfl_xor_sync(0xffffffffu, mx1, 2));

        const float mn0 = fmaxf(mrow0, mx0);
        const float mn1 = fmaxf(mrow1, mx1);
        const float corr0 = ex2(mrow0 - mn0);
        const float corr1 = ex2(mrow1 - mn1);

        float rs0 = 0.f, rs1 = 0.f;
#pragma unroll
        for (int nt = 0; nt < 8; nt++) {
            s[nt][0] = ex2(s[nt][0] - mn0);
            s[nt][1] = ex2(s[nt][1] - mn0);
            s[nt][2] = ex2(s[nt][2] - mn1);
            s[nt][3] = ex2(s[nt][3] - mn1);
            rs0 += s[nt][0] + s[nt][1];
            rs1 += s[nt][2] + s[nt][3];
        }
        rs0 += __shfl_xor_sync(0xffffffffu, rs0, 1);
        rs0 += __shfl_xor_sync(0xffffffffu, rs0, 2);
        rs1 += __shfl_xor_sync(0xffffffffu, rs1, 1);
        rs1 += __shfl_xor_sync(0xffffffffu, rs1, 2);

        lsum0 = lsum0 * corr0 + rs0;
        lsum1 = lsum1 * corr1 + rs1;
        mrow0 = mn0;
        mrow1 = mn1;
#pragma unroll
        for (int nt = 0; nt < 8; nt++) {
            o[nt][0] *= corr0;
            o[nt][1] *= corr0;
            o[nt][2] *= corr1;
            o[nt][3] *= corr1;
        }

        // ---- pack S registers into PV A-fragments (no smem) ----
        uint32_t pf[4][4];
#pragma unroll
        for (int s4 = 0; s4 < 4; s4++) {
            __half2 h0 = __float22half2_rn(make_float2(s[2 * s4][0],     s[2 * s4][1]));
            __half2 h1 = __float22half2_rn(make_float2(s[2 * s4][2],     s[2 * s4][3]));
            __half2 h2 = __float22half2_rn(make_float2(s[2 * s4 + 1][0], s[2 * s4 + 1][1]));
            __half2 h3 = __float22half2_rn(make_float2(s[2 * s4 + 1][2], s[2 * s4 + 1][3]));
            pf[s4][0] = *(uint32_t*)&h0;
            pf[s4][1] = *(uint32_t*)&h1;
            pf[s4][2] = *(uint32_t*)&h2;
            pf[s4][3] = *(uint32_t*)&h3;
        }

        // ---- O += P V (V via ldmatrix.trans) ----
#pragma unroll
        for (int step = 0; step < 4; step++) {
#pragma unroll
            for (int np = 0; np < 4; np++) {
                uint32_t bb[4];
                ldsm4t(bb, vBase + (uint32_t)((step * 16 + vb_row) * ST + np * 16 + vb_col) * 2);
                mma_f16(o[2 * np],     pf[step], bb[0], bb[1]);
                mma_f16(o[2 * np + 1], pf[step], bb[2], bb[3]);
            }
        }
    }

    // write ctx as fp16 [B*S, H*64]
    const int b = bh >> 4;
    const int h = bh & 15;
    const float inv0 = 1.f / lsum0;
    const float inv1 = 1.f / lsum1;
    const int srow = qt * 128 + wid * 16 + lr;
#pragma unroll
    for (int nt = 0; nt < 8; nt++) {
        const int d = nt * 8 + 2 * lq;
        __half2 p0 = __float22half2_rn(make_float2(o[nt][0] * inv0, o[nt][1] * inv0));
        __half2 p1 = __float22half2_rn(make_float2(o[nt][2] * inv1, o[nt][3] * inv1));
        *(uint32_t*)&ctx[(size_t)(b * NS + srow) * NDM + h * 64 + d] = *(uint32_t*)&p0;
        *(uint32_t*)&ctx[(size_t)(b * NS + srow + 8) * NDM + h * 64 + d] = *(uint32_t*)&p1;
    }
}

// ---------------------------------------------------------------------------
// Fused residual + LayerNorm (in-place on out)
// ---------------------------------------------------------------------------
__global__ __launch_bounds__(256) void ln_kernel(const float* __restrict__ Qin,
                                                 const float* __restrict__ gamma,
                                                 const float* __restrict__ beta,
                                                 float* __restrict__ out) {
    __shared__ float rs[8], rq[8], fin[2];
    const int row = blockIdx.x;
    const int tid = threadIdx.x;
    const int c   = tid << 2;

    float4 o4 = *(const float4*)(out + (size_t)row * NDM + c);
    float4 q4 = *(const float4*)(Qin + (size_t)row * NDM + c);
    const float x0 = o4.x + q4.x, x1 = o4.y + q4.y, x2 = o4.z + q4.z, x3 = o4.w + q4.w;
    float s  = x0 + x1 + x2 + x3;
    float sq = x0 * x0 + x1 * x1 + x2 * x2 + x3 * x3;
#pragma unroll
    for (int off = 16; off; off >>= 1) {
        s  += __shfl_xor_sync(0xffffffffu, s, off);
        sq += __shfl_xor_sync(0xffffffffu, sq, off);
    }
    const int wid = tid >> 5, lane = tid & 31;
    if (lane == 0) { rs[wid] = s; rq[wid] = sq; }
    __syncthreads();
    if (tid == 0) {
        float a = 0.f, b2 = 0.f;
#pragma unroll
        for (int i = 0; i < 8; i++) { a += rs[i]; b2 += rq[i]; }
        fin[0] = a;
        fin[1] = b2;
    }
    __syncthreads();
    const float mu   = fin[0] * (1.0f / NDM);
    const float var  = fin[1] * (1.0f / NDM) - mu * mu;
    const float rstd = rsqrtf(var + 1e-5f);

    float4 g4 = *(const float4*)(gamma + c);
    float4 b4 = *(const float4*)(beta + c);
    float4 r;
    r.x = (x0 - mu) * rstd * g4.x + b4.x;
    r.y = (x1 - mu) * rstd * g4.y + b4.y;
    r.z = (x2 - mu) * rstd * g4.z + b4.z;
    r.w = (x3 - mu) * rstd * g4.w + b4.w;
    *(float4*)(out + (size_t)row * NDM + c) = r;
}

// ---------------------------------------------------------------------------
// Launch
// ---------------------------------------------------------------------------
extern "C" void kernel_launch(void* const* d_in, const int* in_sizes, int n_in,
                              void* d_out, int out_size) {
    const float* Q     = (const float*)d_in[0];
    const float* K     = (const float*)d_in[1];
    const float* V     = (const float*)d_in[2];
    const float* W_Q   = (const float*)d_in[3];
    const float* W_K   = (const float*)d_in[4];
    const float* W_V   = (const float*)d_in[5];
    const float* W_O   = (const float*)d_in[6];
    const float* gamma = (const float*)d_in[7];
    const float* beta  = (const float*)d_in[8];
    float* out = (float*)d_out;

    __half *qh, *kh, *vh, *ctxh, *qb, *kb, *vb, *wtq, *wtk, *wtv, *wto;
    cudaGetSymbolAddress((void**)&qh,   g_Qh);
    cudaGetSymbolAddress((void**)&kh,   g_Kh);
    cudaGetSymbolAddress((void**)&vh,   g_Vh);
    cudaGetSymbolAddress((void**)&ctxh, g_ctxh);
    cudaGetSymbolAddress((void**)&qb,   g_Qb);
    cudaGetSymbolAddress((void**)&kb,   g_Kb);
    cudaGetSymbolAddress((void**)&vb,   g_Vb);
    cudaGetSymbolAddress((void**)&wtq,  g_WTq);
    cudaGetSymbolAddress((void**)&wtk,  g_WTk);
    cudaGetSymbolAddress((void**)&wtv,  g_WTv);
    cudaGetSymbolAddress((void**)&wto,  g_WTo);

    cudaFuncSetAttribute(attn_h, cudaFuncAttributeMaxDynamicSharedMemorySize,
                         ATTN_SMEM_BYTES);
    cudaFuncSetAttribute(gemm_qkv, cudaFuncAttributeMaxDynamicSharedMemorySize,
                         GEMM_SMEM);
    cudaFuncSetAttribute(gemm_out, cudaFuncAttributeMaxDynamicSharedMemorySize,
                         GEMM_SMEM);

    // conversions (batched)
    f2h3_kernel<<<dim3(NM * NDM / 1024, 3), 256>>>(Q, K, V, qb, kb, vb);
    wtrans4_kernel<<<dim3(32, 32, 4), 256>>>(W_Q, W_K, W_V, W_O, wtq, wtk, wtv, wto);

    // QKV projections fused in one launch (Q pre-scaled by 0.125*log2e)
    gemm_qkv<<<dim3(NDM / 128, NM / 128, 3), 256, GEMM_SMEM>>>(
        qb, kb, vb, wtq, wtk, wtv, qh, kh, vh);

    // attention (fp16, register-resident P), writes fp16 ctx
    attn_h<<<dim3(NS / 128, NB * NH), 256, ATTN_SMEM_BYTES>>>(qh, kh, vh, ctxh);

    // output projection + residual LN
    gemm_out<<<dim3(NDM / 128, NM / 128), 256, GEMM_SMEM>>>(ctxh, wto, out);
    ln_kernel<<<NM, 256>>>(Q, gamma, beta, out);
}

// round 9
// speedup vs baseline: 7.3531x; 1.0809x over previous
#include <cuda_runtime.h>
#include <cuda_fp16.h>
#include <cstdint>

// Problem constants
#define NB   4
#define NS   2048
#define NDM  1024
#define NH   16
#define NM   (NB * NS)      // 8192 rows

// ---------------------------------------------------------------------------
// Device scratch
// ---------------------------------------------------------------------------
__device__ __half g_Qh[NB * NH * NS * 64];   // fp16 heads [B,H,S,64] (Q pre-scaled)
__device__ __half g_Kh[NB * NH * NS * 64];
__device__ __half g_Vh[NB * NH * NS * 64];
__device__ __half g_ctxh[NM * NDM];          // fp16 ctx [B*S, H*Dv]

__device__ __half g_WTq[NDM * NDM];          // fp16 W^T [n][k]
__device__ __half g_WTk[NDM * NDM];
__device__ __half g_WTv[NDM * NDM];
__device__ __half g_WTo[NDM * NDM];

// scale folded into Q heads: 1/sqrt(64) * log2(e)
#define QSCALE 0.18033688011112042f
#define ONES_H2 0x3C003C00u      // half2(1.0, 1.0)

// ---------------------------------------------------------------------------
// mma / ldmatrix / cp.async helpers
// ---------------------------------------------------------------------------
__device__ __forceinline__ uint32_t smem_u32(const void* p) {
    uint32_t a;
    asm("{ .reg .u64 t; cvta.to.shared.u64 t, %1; cvt.u32.u64 %0, t; }"
        : "=r"(a) : "l"(p));
    return a;
}

__device__ __forceinline__ void ldsm4(uint32_t r[4], uint32_t addr) {
    asm volatile("ldmatrix.sync.aligned.m8n8.x4.shared.b16 {%0,%1,%2,%3}, [%4];"
                 : "=r"(r[0]), "=r"(r[1]), "=r"(r[2]), "=r"(r[3]) : "r"(addr));
}

__device__ __forceinline__ void ldsm4t(uint32_t r[4], uint32_t addr) {
    asm volatile("ldmatrix.sync.aligned.m8n8.x4.trans.shared.b16 {%0,%1,%2,%3}, [%4];"
                 : "=r"(r[0]), "=r"(r[1]), "=r"(r[2]), "=r"(r[3]) : "r"(addr));
}

__device__ __forceinline__ void mma_f16(float c[4], const uint32_t a[4],
                                        uint32_t b0, uint32_t b1) {
    asm volatile(
        "mma.sync.aligned.m16n8k16.row.col.f32.f16.f16.f32 "
        "{%0,%1,%2,%3}, {%4,%5,%6,%7}, {%8,%9}, {%0,%1,%2,%3};"
        : "+f"(c[0]), "+f"(c[1]), "+f"(c[2]), "+f"(c[3])
        : "r"(a[0]), "r"(a[1]), "r"(a[2]), "r"(a[3]), "r"(b0), "r"(b1));
}

__device__ __forceinline__ void cp16(uint32_t dst, const void* src) {
    asm volatile("cp.async.cg.shared.global [%0], [%1], 16;" :: "r"(dst), "l"(src));
}
#define CP_COMMIT() asm volatile("cp.async.commit_group;")
#define CP_WAIT0()  asm volatile("cp.async.wait_group 0;")
#define CP_WAIT2()  asm volatile("cp.async.wait_group 2;")

__device__ __forceinline__ float ex2(float x) {
    float r;
    asm("ex2.approx.f32 %0, %1;" : "=f"(r) : "f"(x));
    return r;
}

// packed half2 exp2 of (a, b)
__device__ __forceinline__ uint32_t ex2h2(float a, float b) {
    __half2 h = __float22half2_rn(make_float2(a, b));
    uint32_t u = *(uint32_t*)&h;
    asm("ex2.approx.f16x2 %0, %0;" : "+r"(u));
    return u;
}

// ---------------------------------------------------------------------------
// Weight transpose: W [k][n] fp32 -> WT [n][k] fp16, batched over z
// ---------------------------------------------------------------------------
__global__ __launch_bounds__(256) void wtrans4_kernel(const float* __restrict__ w0,
                                                      const float* __restrict__ w1,
                                                      const float* __restrict__ w2,
                                                      const float* __restrict__ w3,
                                                      __half* t0, __half* t1,
                                                      __half* t2, __half* t3) {
    __shared__ float t[32][33];
    const int z = blockIdx.z;
    const float* W = (z == 0) ? w0 : (z == 1) ? w1 : (z == 2) ? w2 : w3;
    __half* WT = (z == 0) ? t0 : (z == 1) ? t1 : (z == 2) ? t2 : t3;
    const int tx = threadIdx.x & 31;
    const int ty = threadIdx.x >> 5;
    const int bn = blockIdx.x * 32;
    const int bk = blockIdx.y * 32;
#pragma unroll
    for (int i = 0; i < 4; i++)
        t[ty + 8 * i][tx] = W[(size_t)(bk + ty + 8 * i) * NDM + bn + tx];
    __syncthreads();
#pragma unroll
    for (int i = 0; i < 4; i++)
        WT[(size_t)(bn + ty + 8 * i) * NDM + bk + tx] =
            __float2half(t[tx][ty + 8 * i]);
}

// ---------------------------------------------------------------------------
// GEMM common pieces. BM=128, BN=128, BK=32; 8 warps, warp tile 32x64.
// ---------------------------------------------------------------------------
#define GW 20                        // 32-bit words per smem row
#define GSTG 10240                   // bytes per (A or B) stage
#define GEMM32_SMEM (6 * GSTG)       // A 2 stages + B 4 stages = 61440
#define GEMM16_SMEM (8 * GSTG)       // A+B 4 stages each = 81920

// ---------------------------------------------------------------------------
// QKV projection: A fp32 (direct), B fp16 cp.async 4-stage.
// Epilogue: fp16 heads [B,H,S,64] scaled.
// ---------------------------------------------------------------------------
__global__ __launch_bounds__(256, 2) void gemm_qkv(const float* __restrict__ Qf,
                                                   const float* __restrict__ Kf,
                                                   const float* __restrict__ Vf,
                                                   const __half* __restrict__ wtq,
                                                   const __half* __restrict__ wtk,
                                                   const __half* __restrict__ wtv,
                                                   __half* qh, __half* kh, __half* vh) {
    extern __shared__ __align__(16) uint8_t gsm[];
    const uint32_t base = smem_u32(gsm);

    const int z = blockIdx.z;
    const float* A   = (z == 0) ? Qf : (z == 1) ? Kf : Vf;
    const __half* BT = (z == 0) ? wtq : (z == 1) ? wtk : wtv;
    __half* C        = (z == 0) ? qh : (z == 1) ? kh : vh;
    const float scale = (z == 0) ? QSCALE : 1.0f;

    const int tid  = threadIdx.x;
    const int lane = tid & 31;
    const int wid  = tid >> 5;
    const int lr   = lane >> 2;
    const int lq   = lane & 3;
    const int wm0  = (wid & 3) * 32;
    const int wn0  = (wid >> 2) * 64;
    const int m0   = blockIdx.y * 128;
    const int n0   = blockIdx.x * 128;

    const int a_row = wm0 + (lane & 7) + (lane & 8);
    const int a_wrd = (lane >> 4) << 2;
    const int b_row = wn0 + (lane & 7) + ((lane & 16) >> 1);
    const int b_wrd = (lane & 8) ? 4 : 0;

    // B cp.async mapping: 2x 16B per thread per chunk
    const int br = tid >> 2;          // 0..63
    const int bc = tid & 3;
    const uint8_t* Bg = (const uint8_t*)BT + (size_t)n0 * 2048 + bc * 16;

    auto cpB = [&](int c) {
        const uint32_t bB = base + 2 * GSTG + (uint32_t)(c & 3) * GSTG;
        const size_t koff = (size_t)c * 64;
#pragma unroll
        for (int i = 0; i < 2; i++) {
            const uint32_t so = (uint32_t)((br + 64 * i) * GW + bc * 4) * 4;
            cp16(bB + so, Bg + (size_t)(br + 64 * i) * 2048 + koff);
        }
        CP_COMMIT();
    };

    // A fp32 mapping: 4 float4 per thread per chunk (128 rows x 32 fp32)
    auto ldgA = [&](int c, float4 ra[4]) {
#pragma unroll
        for (int i = 0; i < 4; i++) {
            const int gidx = tid + 256 * i;
            const int r = gidx >> 3, seg = gidx & 7;
            ra[i] = *(const float4*)(A + (size_t)(m0 + r) * NDM + c * 32 + seg * 4);
        }
    };
    auto stsA = [&](int c, const float4 ra[4]) {
        const uint32_t aB = base + (uint32_t)(c & 1) * GSTG;
#pragma unroll
        for (int i = 0; i < 4; i++) {
            const int gidx = tid + 256 * i;
            const int r = gidx >> 3, seg = gidx & 7;
            __half2 h0 = __float22half2_rn(make_float2(ra[i].x, ra[i].y));
            __half2 h1 = __float22half2_rn(make_float2(ra[i].z, ra[i].w));
            uint2 u = make_uint2(*(uint32_t*)&h0, *(uint32_t*)&h1);
            *(uint2*)(gsm + (aB - base) + (uint32_t)(r * GW + seg * 2) * 4) = u;
        }
    };

    float acc[2][8][4];
#pragma unroll
    for (int mi = 0; mi < 2; mi++)
#pragma unroll
        for (int nt = 0; nt < 8; nt++)
#pragma unroll
            for (int v = 0; v < 4; v++) acc[mi][nt][v] = 0.f;

    float4 ra[4];
    ldgA(0, ra);
    cpB(0); cpB(1); cpB(2);
    stsA(0, ra);
    ldgA(1, ra);

    for (int c = 0; c < 32; c++) {
        if (c < 29) CP_WAIT2(); else CP_WAIT0();
        __syncthreads();
        if (c + 3 < 32) cpB(c + 3);
        if (c + 1 < 32) stsA(c + 1, ra);
        if (c + 2 < 32) ldgA(c + 2, ra);

        const uint32_t aB = base + (uint32_t)(c & 1) * GSTG;
        const uint32_t bB = base + 2 * GSTG + (uint32_t)(c & 3) * GSTG;

#pragma unroll
        for (int s = 0; s < 2; s++) {
            uint32_t a[2][4];
            ldsm4(a[0], aB + (uint32_t)((a_row)*GW + s * 8 + a_wrd) * 4);
            ldsm4(a[1], aB + (uint32_t)((a_row + 16) * GW + s * 8 + a_wrd) * 4);
#pragma unroll
            for (int np = 0; np < 4; np++) {
                uint32_t bb[4];
                ldsm4(bb, bB + (uint32_t)((b_row + np * 16) * GW + s * 8 + b_wrd) * 4);
                mma_f16(acc[0][2 * np],     a[0], bb[0], bb[1]);
                mma_f16(acc[1][2 * np],     a[1], bb[0], bb[1]);
                mma_f16(acc[0][2 * np + 1], a[0], bb[2], bb[3]);
                mma_f16(acc[1][2 * np + 1], a[1], bb[2], bb[3]);
            }
        }
    }

    // Epilogue: fp16 heads [B,H,S,64]
#pragma unroll
    for (int mi = 0; mi < 2; mi++) {
        const int row0 = m0 + wm0 + mi * 16 + lr;
#pragma unroll
        for (int nt = 0; nt < 8; nt++) {
            const int col = wn0 + nt * 8 + 2 * lq;
            __half2 v0 = __float22half2_rn(
                make_float2(acc[mi][nt][0] * scale, acc[mi][nt][1] * scale));
            __half2 v1 = __float22half2_rn(
                make_float2(acc[mi][nt][2] * scale, acc[mi][nt][3] * scale));
            const int gcol = n0 + col;
            const int h = gcol >> 6, d = gcol & 63;
            const int b0i = row0 >> 11, s0 = row0 & 2047;
            *(uint32_t*)&C[(size_t)((b0i * NH + h) * NS + s0) * 64 + d] = *(uint32_t*)&v0;
            const int row1 = row0 + 8;
            const int b1i = row1 >> 11, s1 = row1 & 2047;
            *(uint32_t*)&C[(size_t)((b1i * NH + h) * NS + s1) * 64 + d] = *(uint32_t*)&v1;
        }
    }
}

// ---------------------------------------------------------------------------
// Output projection: A fp16 (ctx), 4-stage cp.async both operands.
// Epilogue: fp32 out + residual (Q).
// ---------------------------------------------------------------------------
__global__ __launch_bounds__(256) void gemm_out(const __half* __restrict__ A,
                                                const __half* __restrict__ BT,
                                                float* __restrict__ C,
                                                const float* __restrict__ resid) {
    extern __shared__ __align__(16) uint8_t gsm[];
    const uint32_t base = smem_u32(gsm);

    const int tid  = threadIdx.x;
    const int lane = tid & 31;
    const int wid  = tid >> 5;
    const int lr   = lane >> 2;
    const int lq   = lane & 3;
    const int wm0  = (wid & 3) * 32;
    const int wn0  = (wid >> 2) * 64;
    const int m0   = blockIdx.y * 128;
    const int n0   = blockIdx.x * 128;

    const int a_row = wm0 + (lane & 7) + (lane & 8);
    const int a_wrd = (lane >> 4) << 2;
    const int b_row = wn0 + (lane & 7) + ((lane & 16) >> 1);
    const int b_wrd = (lane & 8) ? 4 : 0;

    const int r0 = tid >> 2;
    const int cu = tid & 3;
    const uint8_t* Ag = (const uint8_t*)A + (size_t)m0 * 2048 + cu * 16;
    const uint8_t* Bg = (const uint8_t*)BT + (size_t)n0 * 2048 + cu * 16;

    auto prefetch = [&](int c) {
        const int stg = c & 3;
        const uint32_t aB = base + (uint32_t)stg * (2 * GSTG);
        const uint32_t bB = aB + GSTG;
        const size_t koff = (size_t)c * 64;
#pragma unroll
        for (int i = 0; i < 2; i++) {
            const uint32_t so = (uint32_t)((r0 + 64 * i) * GW + cu * 4) * 4;
            cp16(aB + so, Ag + (size_t)(r0 + 64 * i) * 2048 + koff);
            cp16(bB + so, Bg + (size_t)(r0 + 64 * i) * 2048 + koff);
        }
        CP_COMMIT();
    };

    float acc[2][8][4];
#pragma unroll
    for (int mi = 0; mi < 2; mi++)
#pragma unroll
        for (int nt = 0; nt < 8; nt++)
#pragma unroll
            for (int v = 0; v < 4; v++) acc[mi][nt][v] = 0.f;

    prefetch(0);
    prefetch(1);
    prefetch(2);

    for (int c = 0; c < 32; c++) {
        if (c < 29) CP_WAIT2(); else CP_WAIT0();
        __syncthreads();
        if (c + 3 < 32) prefetch(c + 3);

        const int stg = c & 3;
        const uint32_t aB = base + (uint32_t)stg * (2 * GSTG);
        const uint32_t bB = aB + GSTG;

#pragma unroll
        for (int s = 0; s < 2; s++) {
            uint32_t a[2][4];
            ldsm4(a[0], aB + (uint32_t)((a_row)*GW + s * 8 + a_wrd) * 4);
            ldsm4(a[1], aB + (uint32_t)((a_row + 16) * GW + s * 8 + a_wrd) * 4);
#pragma unroll
            for (int np = 0; np < 4; np++) {
                uint32_t bb[4];
                ldsm4(bb, bB + (uint32_t)((b_row + np * 16) * GW + s * 8 + b_wrd) * 4);
                mma_f16(acc[0][2 * np],     a[0], bb[0], bb[1]);
                mma_f16(acc[1][2 * np],     a[1], bb[0], bb[1]);
                mma_f16(acc[0][2 * np + 1], a[0], bb[2], bb[3]);
                mma_f16(acc[1][2 * np + 1], a[1], bb[2], bb[3]);
            }
        }
    }

#pragma unroll
    for (int mi = 0; mi < 2; mi++) {
        const int row0 = m0 + wm0 + mi * 16 + lr;
#pragma unroll
        for (int nt = 0; nt < 8; nt++) {
            const int col = n0 + wn0 + nt * 8 + 2 * lq;
            float2 q0 = *(const float2*)&resid[(size_t)row0 * NDM + col];
            float2 q1 = *(const float2*)&resid[(size_t)(row0 + 8) * NDM + col];
            *(float2*)&C[(size_t)row0 * NDM + col] =
                make_float2(acc[mi][nt][0] + q0.x, acc[mi][nt][1] + q0.y);
            *(float2*)&C[(size_t)(row0 + 8) * NDM + col] =
                make_float2(acc[mi][nt][2] + q1.x, acc[mi][nt][3] + q1.y);
        }
    }
}

// ---------------------------------------------------------------------------
// Flash attention, causal, fp16 mma m16n8k16.
// Softmax denominator via MMA-with-ones; P via ex2.approx.f16x2 into packed
// fragments; packed-half max reduction. cp.async double-buffered K/V.
// ---------------------------------------------------------------------------
#define ST 72   // halves per smem row
#define ATTN_SMEM_BYTES ((128 + 2 * 64 + 2 * 64) * ST * 2)   // 55296

__global__ __launch_bounds__(256, 2) void attn_h(const __half* __restrict__ Qh,
                                                 const __half* __restrict__ Kh,
                                                 const __half* __restrict__ Vh,
                                                 __half* __restrict__ ctx) {
    extern __shared__ __half smh[];
    __half* Qs = smh;                         // [128][ST]
    __half* Ks0 = Qs + 128 * ST;              // [2][64][ST]
    __half* Vs0 = Ks0 + 2 * 64 * ST;          // [2][64][ST]
    const uint32_t qsU = smem_u32(Qs);
    const uint32_t ksU = smem_u32(Ks0);
    const uint32_t vsU = smem_u32(Vs0);
    const uint32_t KVSTG = 64 * ST * 2;       // bytes per stage

    const int tid  = threadIdx.x;
    const int lane = tid & 31;
    const int wid  = tid >> 5;
    const int lr   = lane >> 2;
    const int lq   = lane & 3;

    const int qt = gridDim.x - 1 - blockIdx.x;   // heavy tiles first
    const int bh = blockIdx.y;

    const __half* Qb = Qh + (size_t)bh * NS * 64;
    const __half* Kb = Kh + (size_t)bh * NS * 64;
    const __half* Vb = Vh + (size_t)bh * NS * 64;

    auto prefetch = [&](int kt, int st) {
#pragma unroll
        for (int i = 0; i < 2; i++) {
            const int idx = tid + 256 * i;
            const int r = idx >> 3, cu = idx & 7;
            cp16(ksU + (uint32_t)st * KVSTG + (uint32_t)(r * ST + cu * 8) * 2,
                 Kb + (size_t)(kt * 64 + r) * 64 + cu * 8);
            cp16(vsU + (uint32_t)st * KVSTG + (uint32_t)(r * ST + cu * 8) * 2,
                 Vb + (size_t)(kt * 64 + r) * 64 + cu * 8);
        }
        CP_COMMIT();
    };

    prefetch(0, 0);
#pragma unroll
    for (int i = 0; i < 4; i++) {
        const int idx = tid + 256 * i;
        const int r = idx >> 3, cu = idx & 7;
        *(uint4*)&Qs[r * ST + cu * 8] =
            *(const uint4*)(Qb + (size_t)(qt * 128 + r) * 64 + cu * 8);
    }
    __syncthreads();

    uint32_t qf[4][4];
    {
        const int arow = wid * 16 + (lane & 7) + (lane & 8);
        const int acol = (lane & 16) >> 1;
#pragma unroll
        for (int s = 0; s < 4; s++)
            ldsm4(qf[s], qsU + (uint32_t)(arow * ST + s * 16 + acol) * 2);
    }

    float o[8][4];
#pragma unroll
    for (int nt = 0; nt < 8; nt++)
#pragma unroll
        for (int v = 0; v < 4; v++) o[nt][v] = 0.f;
    float osum[4] = {0.f, 0.f, 0.f, 0.f};     // row-sum accumulator (P @ ones)
    float mrow0 = -1e30f, mrow1 = -1e30f;

    const int qrow0 = qt * 128 + wid * 16 + lr;
    const int qrow1 = qrow0 + 8;
    const int ktmax = 2 * qt + 1;

    const int kb_row = (lane & 7) + ((lane & 16) >> 1);
    const int kb_col = (lane & 8) ? 8 : 0;
    const int vb_row = (lane & 7) + (lane & 8);
    const int vb_col = (lane & 16) >> 1;

    for (int kt = 0; kt <= ktmax; kt++) {
        const int st = kt & 1;
        CP_WAIT0();
        __syncthreads();
        if (kt < ktmax) prefetch(kt + 1, st ^ 1);

        const uint32_t kBase = ksU + (uint32_t)st * KVSTG;
        const uint32_t vBase = vsU + (uint32_t)st * KVSTG;

        // ---- S = Q K^T (log2 domain; QSCALE folded into Q) ----
        float s[8][4];
#pragma unroll
        for (int nt = 0; nt < 8; nt++)
#pragma unroll
            for (int v = 0; v < 4; v++) s[nt][v] = 0.f;

#pragma unroll
        for (int step = 0; step < 4; step++) {
#pragma unroll
            for (int np = 0; np < 4; np++) {
                uint32_t bb[4];
                ldsm4(bb, kBase + (uint32_t)((np * 16 + kb_row) * ST + step * 16 + kb_col) * 2);
                mma_f16(s[2 * np],     qf[step], bb[0], bb[1]);
                mma_f16(s[2 * np + 1], qf[step], bb[2], bb[3]);
            }
        }

        // causal mask (diagonal tiles only)
        if (kt >= 2 * qt) {
#pragma unroll
            for (int nt = 0; nt < 8; nt++) {
                const int col = kt * 64 + nt * 8 + 2 * lq;
                if (col     > qrow0) s[nt][0] = -1e30f;
                if (col + 1 > qrow0) s[nt][1] = -1e30f;
                if (col     > qrow1) s[nt][2] = -1e30f;
                if (col + 1 > qrow1) s[nt][3] = -1e30f;
            }
        }

        // ---- row max (packed half2 butterfly over quad lanes) ----
        float mx0 = -1e30f, mx1 = -1e30f;
#pragma unroll
        for (int nt = 0; nt < 8; nt++) {
            mx0 = fmaxf(mx0, fmaxf(s[nt][0], s[nt][1]));
            mx1 = fmaxf(mx1, fmaxf(s[nt][2], s[nt][3]));
        }
        __half2 mxh = __float22half2_rn(make_float2(mx0, mx1));
#pragma unroll
        for (int off = 1; off < 4; off <<= 1) {
            uint32_t mu = *(uint32_t*)&mxh;
            uint32_t ou = __shfl_xor_sync(0xffffffffu, mu, off);
            mxh = __hmax2(mxh, *(__half2*)&ou);
        }
        float2 mxf = __half22float2(mxh);
        const float mn0 = fmaxf(mrow0, mxf.x);
        const float mn1 = fmaxf(mrow1, mxf.y);
        const float corr0 = ex2(mrow0 - mn0);
        const float corr1 = ex2(mrow1 - mn1);
        mrow0 = mn0;
        mrow1 = mn1;

        // ---- P fragments via packed f16x2 exp2 (no smem, no sum shuffles) ----
        uint32_t pf[4][4];
#pragma unroll
        for (int s4 = 0; s4 < 4; s4++) {
            pf[s4][0] = ex2h2(s[2 * s4][0] - mn0,     s[2 * s4][1] - mn0);
            pf[s4][1] = ex2h2(s[2 * s4][2] - mn1,     s[2 * s4][3] - mn1);
            pf[s4][2] = ex2h2(s[2 * s4 + 1][0] - mn0, s[2 * s4 + 1][1] - mn0);
            pf[s4][3] = ex2h2(s[2 * s4 + 1][2] - mn1, s[2 * s4 + 1][3] - mn1);
        }

        // ---- rescale accumulators ----
#pragma unroll
        for (int nt = 0; nt < 8; nt++) {
            o[nt][0] *= corr0;
            o[nt][1] *= corr0;
            o[nt][2] *= corr1;
            o[nt][3] *= corr1;
        }
        osum[0] *= corr0;
        osum[1] *= corr0;
        osum[2] *= corr1;
        osum[3] *= corr1;

        // ---- O += P V; denominator via MMA with all-ones B ----
#pragma unroll
        for (int step = 0; step < 4; step++) {
#pragma unroll
            for (int np = 0; np < 4; np++) {
                uint32_t bb[4];
                ldsm4t(bb, vBase + (uint32_t)((step * 16 + vb_row) * ST + np * 16 + vb_col) * 2);
                mma_f16(o[2 * np],     pf[step], bb[0], bb[1]);
                mma_f16(o[2 * np + 1], pf[step], bb[2], bb[3]);
            }
            mma_f16(osum, pf[step], ONES_H2, ONES_H2);
        }
    }

    // write ctx as fp16 [B*S, H*64]
    const int b = bh >> 4;
    const int h = bh & 15;
    const float inv0 = 1.f / osum[0];
    const float inv1 = 1.f / osum[2];
    const int srow = qt * 128 + wid * 16 + lr;
#pragma unroll
    for (int nt = 0; nt < 8; nt++) {
        const int d = nt * 8 + 2 * lq;
        __half2 p0 = __float22half2_rn(make_float2(o[nt][0] * inv0, o[nt][1] * inv0));
        __half2 p1 = __float22half2_rn(make_float2(o[nt][2] * inv1, o[nt][3] * inv1));
        *(uint32_t*)&ctx[(size_t)(b * NS + srow) * NDM + h * 64 + d] = *(uint32_t*)&p0;
        *(uint32_t*)&ctx[(size_t)(b * NS + srow + 8) * NDM + h * 64 + d] = *(uint32_t*)&p1;
    }
}

// ---------------------------------------------------------------------------
// LayerNorm (residual already folded in by gemm_out), in-place on out.
// ---------------------------------------------------------------------------
__global__ __launch_bounds__(256) void ln_kernel(const float* __restrict__ gamma,
                                                 const float* __restrict__ beta,
                                                 float* __restrict__ out) {
    __shared__ float rs[8], rq[8], fin[2];
    const int row = blockIdx.x;
    const int tid = threadIdx.x;
    const int c   = tid << 2;

    float4 x4 = *(const float4*)(out + (size_t)row * NDM + c);
    const float x0 = x4.x, x1 = x4.y, x2 = x4.z, x3 = x4.w;
    float s  = x0 + x1 + x2 + x3;
    float sq = x0 * x0 + x1 * x1 + x2 * x2 + x3 * x3;
#pragma unroll
    for (int off = 16; off; off >>= 1) {
        s  += __shfl_xor_sync(0xffffffffu, s, off);
        sq += __shfl_xor_sync(0xffffffffu, sq, off);
    }
    const int wid = tid >> 5, lane = tid & 31;
    if (lane == 0) { rs[wid] = s; rq[wid] = sq; }
    __syncthreads();
    if (tid == 0) {
        float a = 0.f, b2 = 0.f;
#pragma unroll
        for (int i = 0; i < 8; i++) { a += rs[i]; b2 += rq[i]; }
        fin[0] = a;
        fin[1] = b2;
    }
    __syncthreads();
    const float mu   = fin[0] * (1.0f / NDM);
    const float var  = fin[1] * (1.0f / NDM) - mu * mu;
    const float rstd = rsqrtf(var + 1e-5f);

    float4 g4 = *(const float4*)(gamma + c);
    float4 b4 = *(const float4*)(beta + c);
    float4 r;
    r.x = (x0 - mu) * rstd * g4.x + b4.x;
    r.y = (x1 - mu) * rstd * g4.y + b4.y;
    r.z = (x2 - mu) * rstd * g4.z + b4.z;
    r.w = (x3 - mu) * rstd * g4.w + b4.w;
    *(float4*)(out + (size_t)row * NDM + c) = r;
}

// ---------------------------------------------------------------------------
// Launch
// ---------------------------------------------------------------------------
extern "C" void kernel_launch(void* const* d_in, const int* in_sizes, int n_in,
                              void* d_out, int out_size) {
    const float* Q     = (const float*)d_in[0];
    const float* K     = (const float*)d_in[1];
    const float* V     = (const float*)d_in[2];
    const float* W_Q   = (const float*)d_in[3];
    const float* W_K   = (const float*)d_in[4];
    const float* W_V   = (const float*)d_in[5];
    const float* W_O   = (const float*)d_in[6];
    const float* gamma = (const float*)d_in[7];
    const float* beta  = (const float*)d_in[8];
    float* out = (float*)d_out;

    __half *qh, *kh, *vh, *ctxh, *wtq, *wtk, *wtv, *wto;
    cudaGetSymbolAddress((void**)&qh,   g_Qh);
    cudaGetSymbolAddress((void**)&kh,   g_Kh);
    cudaGetSymbolAddress((void**)&vh,   g_Vh);
    cudaGetSymbolAddress((void**)&ctxh, g_ctxh);
    cudaGetSymbolAddress((void**)&wtq,  g_WTq);
    cudaGetSymbolAddress((void**)&wtk,  g_WTk);
    cudaGetSymbolAddress((void**)&wtv,  g_WTv);
    cudaGetSymbolAddress((void**)&wto,  g_WTo);

    cudaFuncSetAttribute(attn_h, cudaFuncAttributeMaxDynamicSharedMemorySize,
                         ATTN_SMEM_BYTES);
    cudaFuncSetAttribute(gemm_qkv, cudaFuncAttributeMaxDynamicSharedMemorySize,
                         GEMM32_SMEM);
    cudaFuncSetAttribute(gemm_out, cudaFuncAttributeMaxDynamicSharedMemorySize,
                         GEMM16_SMEM);

    // weight transposes (fp32 -> fp16 W^T)
    wtrans4_kernel<<<dim3(32, 32, 4), 256>>>(W_Q, W_K, W_V, W_O, wtq, wtk, wtv, wto);

    // QKV projections straight from fp32 inputs (Q pre-scaled by 0.125*log2e)
    gemm_qkv<<<dim3(NDM / 128, NM / 128, 3), 256, GEMM32_SMEM>>>(
        Q, K, V, wtq, wtk, wtv, qh, kh, vh);

    // attention (fp16, register P, MMA row-sums), writes fp16 ctx
    attn_h<<<dim3(NS / 128, NB * NH), 256, ATTN_SMEM_BYTES>>>(qh, kh, vh, ctxh);

    // output projection + fused residual, then LN
    gemm_out<<<dim3(NDM / 128, NM / 128), 256, GEMM16_SMEM>>>(ctxh, wto, out, Q);
    ln_kernel<<<NM, 256>>>(gamma, beta, out);
}